// round 6
// baseline (speedup 1.0000x reference)
#include <cuda_runtime.h>
#include <cuda_pipeline.h>

typedef unsigned long long u64;

// ---- packed f32x2 helpers (exact IEEE fp32 per lane) ---------------------------
__device__ __forceinline__ u64 pk2(float lo, float hi) {
    u64 r; asm("mov.b64 %0, {%1, %2};" : "=l"(r) : "f"(lo), "f"(hi)); return r;
}
__device__ __forceinline__ void fma2(u64& d, u64 a, u64 b) {
    asm("fma.rn.f32x2 %0, %1, %2, %3;" : "=l"(d) : "l"(a), "l"(b), "l"(d));
}
__device__ __forceinline__ float2 up2(u64 v) {
    float lo, hi; asm("mov.b64 {%0, %1}, %2;" : "=f"(lo), "=f"(hi) : "l"(v));
    return make_float2(lo, hi);
}

// ---------------- scratch (static device globals; no allocation) ----------------
__device__ float g_h1 [16 * 64 * 128 * 128];
__device__ float g_h2 [16 * 128 * 64 * 64];
__device__ float g_h3 [16 * 128 * 64 * 64];
__device__ float g_h3r[16 * 128 * 64 * 64];
__device__ float g_t  [2 * 16 * 32 * 64 * 64];
__device__ float g_z  [16 * 4096 * 4];
// weights transposed to [ci][kh][kw][oc] (oc contiguous -> natural u64 oc-pairs)
__device__ float g_w2t [64 * 4 * 4 * 128];
__device__ float g_w3t [128 * 3 * 3 * 128];
__device__ float g_wr1t[128 * 3 * 3 * 32];
__device__ float g_wr2t[128 * 3 * 3 * 32];

// ------------- transpose weights to oc-innermost --------------------------------
__global__ void k_padw(const float* __restrict__ w2, const float* __restrict__ w3,
                       const float* __restrict__ r1, const float* __restrict__ r2) {
    const int i = blockIdx.x * 256 + threadIdx.x;
    if (i < 131072) {                      // conv2: [oc128][ci64][kh4][kw4]
        const int oc = i >> 10, r = i & 1023;          // r = ci*16 + kh*4 + kw
        g_w2t[r * 128 + oc] = w2[i];
    } else if (i < 131072 + 147456) {      // conv3: [oc128][ci128][9]
        const int j = i - 131072, oc = j / 1152, r = j % 1152;
        g_w3t[r * 128 + oc] = w3[j];
    } else if (i < 131072 + 147456 + 36864) {
        const int j = i - 131072 - 147456, oc = j / 1152, r = j % 1152;
        g_wr1t[r * 32 + oc] = r1[j];
    } else if (i < 131072 + 147456 + 73728) {
        const int j = i - 131072 - 147456 - 36864, oc = j / 1152, r = j % 1152;
        g_wr2t[r * 32 + oc] = r2[j];
    }
}

// ---------------- conv1: [16,1,256,256] -> relu -> [16,64,128,128], k4 s2 p1 ----
__global__ void k_conv1(const float* __restrict__ x, const float* __restrict__ w,
                        const float* __restrict__ b) {
    const int oy = blockIdx.x, bb = blockIdx.y, ox = threadIdx.x;
    __shared__ float sw[64 * 16];
    __shared__ float sb[64];
    for (int i = threadIdx.x; i < 64 * 16; i += 128) sw[i] = w[i];
    if (threadIdx.x < 64) sb[threadIdx.x] = b[threadIdx.x];
    __syncthreads();

    const float* xb = x + bb * 256 * 256;
    float iv[16];
#pragma unroll
    for (int kh = 0; kh < 4; kh++) {
        const int iy = 2 * oy - 1 + kh;
#pragma unroll
        for (int kw = 0; kw < 4; kw++) {
            const int ix = 2 * ox - 1 + kw;
            iv[kh * 4 + kw] = (iy >= 0 && iy < 256 && ix >= 0 && ix < 256)
                                  ? xb[iy * 256 + ix] : 0.f;
        }
    }
    float* ob = g_h1 + bb * 64 * 16384 + oy * 128 + ox;
    for (int oc = 0; oc < 64; oc++) {
        float a = sb[oc];
#pragma unroll
        for (int t = 0; t < 16; t++) a += iv[t] * sw[oc * 16 + t];
        ob[oc * 16384] = fmaxf(a, 0.f);
    }
}

// ---------------- conv2: k4 s2 p1, FFMA2 over oc pairs --------------------------
// block 128 = 16 xg (4px) x 8 rows; 16oc x 4px per thread
__global__ __launch_bounds__(128) void k_conv2(const float* __restrict__ wt,
                                               const float* __restrict__ b) {
    // grid (8 oy-tiles, 8 ocg, 16 batch)
    const int oy0 = blockIdx.x * 8, ocb = blockIdx.y * 16, bb = blockIdx.z;
    const int tid = threadIdx.x, txx = tid & 15, tyy = tid >> 4;

    __shared__ __align__(16) float s_in[2][2][18][136];  // interior [4..131]
    __shared__ __align__(16) float s_w [2][2][4][4][16]; // [ci][kh][kw][oc]

    for (int i = tid; i < 2 * 2 * 18; i += 128) {
        const int bf = i / 36, r = i % 36, ci = r / 18, row = r % 18;
        s_in[bf][ci][row][3]   = 0.f;
        s_in[bf][ci][row][132] = 0.f;
    }

    const float* inb = g_h1 + bb * 64 * 16384;

    auto stage = [&](int it, int bf) {
        const int c0 = it * 2;
        for (int i = tid; i < 1152; i += 128) {  // 2ci x 18row x 32 seg
            const int ci = i / 576, r = i % 576, row = r / 32, seg = r % 32;
            const int iy = 2 * oy0 - 1 + row;
            float* dst = &s_in[bf][ci][row][4 + seg * 4];
            if (iy >= 0 && iy < 128)
                __pipeline_memcpy_async(dst, inb + (c0 + ci) * 16384 + iy * 128 + seg * 4, 16);
            else
                *(float4*)dst = make_float4(0.f, 0.f, 0.f, 0.f);
        }
        for (int i = tid; i < 128; i += 128) {   // 2ci x 16 taps x 4 quads
            const int row = i >> 2, q = i & 3;   // row = ci*16 + kh*4 + kw
            __pipeline_memcpy_async(&((float*)s_w[bf])[row * 16 + q * 4],
                                    wt + (c0 * 16 + row) * 128 + ocb + q * 4, 16);
        }
    };

    u64 acc[8][4];  // [oc pair][px]
#pragma unroll
    for (int j = 0; j < 8; j++) {
        const u64 bv = pk2(b[ocb + 2 * j], b[ocb + 2 * j + 1]);
#pragma unroll
        for (int p = 0; p < 4; p++) acc[j][p] = bv;
    }

    stage(0, 0);
    __pipeline_commit();
    int cur = 0;
    for (int it = 0; it < 32; it++) {
        __pipeline_wait_prior(0);
        __syncthreads();
        if (it + 1 < 32) { stage(it + 1, cur ^ 1); __pipeline_commit(); }
#pragma unroll
        for (int ci = 0; ci < 2; ci++) {
#pragma unroll
            for (int kh = 0; kh < 4; kh++) {
                const float* rp = &s_in[cur][ci][2 * tyy + kh][8 * txx];
                const float4 A = *(const float4*)rp;
                const float4 B = *(const float4*)(rp + 4);
                const float4 C = *(const float4*)(rp + 8);
                const float  D = rp[12];
                u64 bv[10];
                bv[0] = pk2(A.w, A.w); bv[1] = pk2(B.x, B.x);
                bv[2] = pk2(B.y, B.y); bv[3] = pk2(B.z, B.z);
                bv[4] = pk2(B.w, B.w); bv[5] = pk2(C.x, C.x);
                bv[6] = pk2(C.y, C.y); bv[7] = pk2(C.z, C.z);
                bv[8] = pk2(C.w, C.w); bv[9] = pk2(D, D);
#pragma unroll
                for (int kw = 0; kw < 4; kw++) {
                    const u64* wb = (const u64*)&s_w[cur][ci][kh][kw][0];
                    const ulonglong2 W0 = *(const ulonglong2*)wb;
                    const ulonglong2 W1 = *(const ulonglong2*)(wb + 2);
                    const ulonglong2 W2 = *(const ulonglong2*)(wb + 4);
                    const ulonglong2 W3 = *(const ulonglong2*)(wb + 6);
                    const u64 w[8] = {W0.x, W0.y, W1.x, W1.y, W2.x, W2.y, W3.x, W3.y};
#pragma unroll
                    for (int j = 0; j < 8; j++)
#pragma unroll
                        for (int p = 0; p < 4; p++)
                            fma2(acc[j][p], bv[2 * p + kw], w[j]);
                }
            }
        }
        cur ^= 1;
    }
    float* ob = g_h2 + (bb * 128 + ocb) * 4096 + (oy0 + tyy) * 64 + 4 * txx;
#pragma unroll
    for (int j = 0; j < 8; j++) {
        const float2 f0 = up2(acc[j][0]), f1 = up2(acc[j][1]);
        const float2 f2 = up2(acc[j][2]), f3 = up2(acc[j][3]);
        *(float4*)(ob + (2 * j) * 4096) = make_float4(
            fmaxf(f0.x, 0.f), fmaxf(f1.x, 0.f), fmaxf(f2.x, 0.f), fmaxf(f3.x, 0.f));
        *(float4*)(ob + (2 * j + 1) * 4096) = make_float4(
            fmaxf(f0.y, 0.f), fmaxf(f1.y, 0.f), fmaxf(f2.y, 0.f), fmaxf(f3.y, 0.f));
    }
}

// ------- generic 3x3 s1 p1 conv on 64x64, FFMA2, 4 oc-pairs x 8 px --------------
// block 128 = 8 xg (8px) x 16 rows; 8oc x 8px per thread
template <bool ADD_BIAS, bool WRITE_RELU>
__global__ __launch_bounds__(128) void k_c3(
    const float* __restrict__ in, const float* __restrict__ wt,
    const float* __restrict__ bias, float* __restrict__ out,
    float* __restrict__ outr, int COUT, int CIN_TOTAL, int CI_COUNT, int NSPLIT) {
    // grid (4 oy-tiles of 16, COUT/8, 16*NSPLIT)
    const int oy0 = blockIdx.x * 16, ocb = blockIdx.y * 8;
    const int half = blockIdx.z % NSPLIT, bb = blockIdx.z / NSPLIT;
    const int ci0 = half * CI_COUNT;
    const int tid = threadIdx.x, txx = tid & 7, tyy = tid >> 3;

    __shared__ __align__(16) float s_in[2][4][18][72];   // interior [4..67]
    __shared__ __align__(16) float s_w [2][4][3][3][8];  // [ci][kh][kw][oc8]

    for (int i = tid; i < 2 * 4 * 18; i += 128) {
        const int bf = i / 72, r = i % 72, ci = r / 18, row = r % 18;
        s_in[bf][ci][row][3]  = 0.f;
        s_in[bf][ci][row][68] = 0.f;
    }

    const float* inb = in + bb * CIN_TOTAL * 4096;

    auto stage = [&](int it, int bf) {
        const int c0 = ci0 + it * 4;
        for (int i = tid; i < 1152; i += 128) {  // 4ci x 18row x 16 seg
            const int ci = i / 288, r = i % 288, row = r / 16, seg = r % 16;
            const int iy = oy0 - 1 + row;
            float* dst = &s_in[bf][ci][row][4 + seg * 4];
            if (iy >= 0 && iy < 64)
                __pipeline_memcpy_async(dst, inb + (c0 + ci) * 4096 + iy * 64 + seg * 4, 16);
            else
                *(float4*)dst = make_float4(0.f, 0.f, 0.f, 0.f);
        }
        for (int i = tid; i < 72; i += 128) {    // 4ci x 9 taps x 2 quads
            const int row = i >> 1, q = i & 1;   // row = ci*9 + kh*3 + kw
            __pipeline_memcpy_async(&((float*)s_w[bf])[row * 8 + q * 4],
                                    wt + (c0 * 9 + row) * COUT + ocb + q * 4, 16);
        }
    };

    u64 acc[4][8];  // [oc pair][px]
#pragma unroll
    for (int j = 0; j < 4; j++) {
        const float b0 = ADD_BIAS ? bias[ocb + 2 * j] : 0.f;
        const float b1 = ADD_BIAS ? bias[ocb + 2 * j + 1] : 0.f;
        const u64 bv = pk2(b0, b1);
#pragma unroll
        for (int p = 0; p < 8; p++) acc[j][p] = bv;
    }

    const int NITER = CI_COUNT / 4;
    stage(0, 0);
    __pipeline_commit();
    int cur = 0;
    for (int it = 0; it < NITER; it++) {
        __pipeline_wait_prior(0);
        __syncthreads();
        if (it + 1 < NITER) { stage(it + 1, cur ^ 1); __pipeline_commit(); }
#pragma unroll
        for (int ci = 0; ci < 4; ci++) {
#pragma unroll
            for (int kh = 0; kh < 3; kh++) {
                const float* rp = &s_in[cur][ci][tyy + kh][8 * txx];
                const float4 A = *(const float4*)rp;        // abs x-4..x-1 (use .w)
                const float4 B = *(const float4*)(rp + 4);  // x..x+3
                const float4 C = *(const float4*)(rp + 8);  // x+4..x+7
                const float  D = rp[12];                    // x+8
                u64 bv[10];
                bv[0] = pk2(A.w, A.w); bv[1] = pk2(B.x, B.x);
                bv[2] = pk2(B.y, B.y); bv[3] = pk2(B.z, B.z);
                bv[4] = pk2(B.w, B.w); bv[5] = pk2(C.x, C.x);
                bv[6] = pk2(C.y, C.y); bv[7] = pk2(C.z, C.z);
                bv[8] = pk2(C.w, C.w); bv[9] = pk2(D, D);
#pragma unroll
                for (int kw = 0; kw < 3; kw++) {
                    const u64* wb = (const u64*)&s_w[cur][ci][kh][kw][0];
                    const ulonglong2 W0 = *(const ulonglong2*)wb;
                    const ulonglong2 W1 = *(const ulonglong2*)(wb + 2);
                    const u64 w[4] = {W0.x, W0.y, W1.x, W1.y};
#pragma unroll
                    for (int j = 0; j < 4; j++)
#pragma unroll
                        for (int p = 0; p < 8; p++)
                            fma2(acc[j][p], bv[p + kw], w[j]);
                }
            }
        }
        cur ^= 1;
    }
    const int off = ((half * 16 + bb) * COUT + ocb) * 4096 + (oy0 + tyy) * 64 + 8 * txx;
#pragma unroll
    for (int j = 0; j < 4; j++) {
        float lo[8], hi[8];
#pragma unroll
        for (int p = 0; p < 8; p++) {
            const float2 f = up2(acc[j][p]);
            lo[p] = f.x; hi[p] = f.y;
        }
        *(float4*)(out + off + (2 * j) * 4096)     = make_float4(lo[0], lo[1], lo[2], lo[3]);
        *(float4*)(out + off + (2 * j) * 4096 + 4) = make_float4(lo[4], lo[5], lo[6], lo[7]);
        *(float4*)(out + off + (2 * j + 1) * 4096)     = make_float4(hi[0], hi[1], hi[2], hi[3]);
        *(float4*)(out + off + (2 * j + 1) * 4096 + 4) = make_float4(hi[4], hi[5], hi[6], hi[7]);
        if (WRITE_RELU) {
            *(float4*)(outr + off + (2 * j) * 4096) = make_float4(
                fmaxf(lo[0], 0.f), fmaxf(lo[1], 0.f), fmaxf(lo[2], 0.f), fmaxf(lo[3], 0.f));
            *(float4*)(outr + off + (2 * j) * 4096 + 4) = make_float4(
                fmaxf(lo[4], 0.f), fmaxf(lo[5], 0.f), fmaxf(lo[6], 0.f), fmaxf(lo[7], 0.f));
            *(float4*)(outr + off + (2 * j + 1) * 4096) = make_float4(
                fmaxf(hi[0], 0.f), fmaxf(hi[1], 0.f), fmaxf(hi[2], 0.f), fmaxf(hi[3], 0.f));
            *(float4*)(outr + off + (2 * j + 1) * 4096 + 4) = make_float4(
                fmaxf(hi[4], 0.f), fmaxf(hi[5], 0.f), fmaxf(hi[6], 0.f), fmaxf(hi[7], 0.f));
        }
    }
}

// ------- residual 1x1: h3 += b1x1 + W(32->64oc) * relu(t0+t1+bt); h3r = relu ----
__global__ void k_res1x1_add(const float* __restrict__ w, const float* __restrict__ b,
                             const float* __restrict__ bt) {
    const int xy0 = blockIdx.x * 64, ocb = blockIdx.y * 64, bb = blockIdx.z, tx = threadIdx.x;
    __shared__ float  s_t[32][64];
    __shared__ float4 s_w4[64][8];

    const float* t0 = g_t + bb * 32 * 4096 + xy0;
    const float* t1 = g_t + (16 + bb) * 32 * 4096 + xy0;
    for (int i = tx; i < 32 * 64; i += 64) {
        const int ci = i / 64, xx = i % 64;
        s_t[ci][xx] = fmaxf(t0[ci * 4096 + xx] + t1[ci * 4096 + xx] + bt[ci], 0.f);
    }
    for (int i = tx; i < 64 * 32; i += 64) {
        const int o = i / 32, ci = i % 32;
        ((float*)&s_w4[o][0])[ci] = w[(ocb + o) * 32 + ci];
    }
    __syncthreads();

    float acc[64];
#pragma unroll
    for (int o = 0; o < 64; o++) acc[o] = b[ocb + o];
    for (int cq = 0; cq < 8; cq++) {
        const float v0 = s_t[cq * 4 + 0][tx];
        const float v1 = s_t[cq * 4 + 1][tx];
        const float v2 = s_t[cq * 4 + 2][tx];
        const float v3 = s_t[cq * 4 + 3][tx];
#pragma unroll
        for (int o = 0; o < 64; o++) {
            const float4 wv = s_w4[o][cq];
            acc[o] += v0 * wv.x + v1 * wv.y + v2 * wv.z + v3 * wv.w;
        }
    }
    float* hb  = g_h3  + (bb * 128 + ocb) * 4096 + xy0 + tx;
    float* hrb = g_h3r + (bb * 128 + ocb) * 4096 + xy0 + tx;
#pragma unroll
    for (int o = 0; o < 64; o++) {
        const float hv = hb[o * 4096] + acc[o];
        hb[o * 4096]  = hv;
        hrb[o * 4096] = fmaxf(hv, 0.f);
    }
}

// ------- pre-VQ 1x1: z[pos][4] = W(128->4) * h3r + bias -------------------------
__global__ void k_z(const float* __restrict__ w, const float* __restrict__ b) {
    const int xy0 = blockIdx.x * 64, bb = blockIdx.y, tx = threadIdx.x;
    __shared__ float s_h[128][64];
    __shared__ float s_w[4][128];

    const float* hb = g_h3r + bb * 128 * 4096 + xy0;
    for (int i = tx; i < 128 * 64; i += 64) {
        const int ci = i / 64, xx = i % 64;
        s_h[ci][xx] = hb[ci * 4096 + xx];
    }
    for (int i = tx; i < 512; i += 64) s_w[i / 128][i % 128] = w[i];
    __syncthreads();

    float a0 = b[0], a1 = b[1], a2 = b[2], a3 = b[3];
#pragma unroll 4
    for (int ci = 0; ci < 128; ci++) {
        const float hv = s_h[ci][tx];
        a0 += hv * s_w[0][ci];
        a1 += hv * s_w[1][ci];
        a2 += hv * s_w[2][ci];
        a3 += hv * s_w[3][ci];
    }
    ((float4*)g_z)[bb * 4096 + xy0 + tx] = make_float4(a0, a1, a2, a3);
}

// ------- cosine VQ: argmax_k <z, e_k/||e_k||>, gather codebook ------------------
__global__ void k_vq(const float* __restrict__ cb, float* __restrict__ out) {
    const int bb = blockIdx.y;
    const int p0 = (blockIdx.x * 256 + threadIdx.x) * 2;
    __shared__ float4 s_en[2048];
    for (int k = threadIdx.x; k < 2048; k += 256) {
        const float4 c = ((const float4*)cb)[k];
        const float n = sqrtf(c.x * c.x + c.y * c.y + c.z * c.z + c.w * c.w);
        const float inv = 1.f / (n + 1e-12f);
        s_en[k] = make_float4(c.x * inv, c.y * inv, c.z * inv, c.w * inv);
    }
    __syncthreads();

    float4 z[2];
#pragma unroll
    for (int q = 0; q < 2; q++) z[q] = ((const float4*)g_z)[bb * 4096 + p0 + q];

    float best[2] = {-1e30f, -1e30f};
    int bi[2] = {0, 0};
#pragma unroll 4
    for (int k = 0; k < 2048; k++) {
        const float4 e = s_en[k];
#pragma unroll
        for (int q = 0; q < 2; q++) {
            const float s = z[q].x * e.x + z[q].y * e.y + z[q].z * e.z + z[q].w * e.w;
            if (s > best[q]) { best[q] = s; bi[q] = k; }  // strict >: first max (JAX)
        }
    }
    const float4 q0 = ((const float4*)cb)[bi[0]];
    const float4 q1 = ((const float4*)cb)[bi[1]];
    float* ob = out + bb * 4 * 4096 + p0;
    *(float2*)(ob)            = make_float2(q0.x, q1.x);
    *(float2*)(ob + 4096)     = make_float2(q0.y, q1.y);
    *(float2*)(ob + 2 * 4096) = make_float2(q0.z, q1.z);
    *(float2*)(ob + 3 * 4096) = make_float2(q0.w, q1.w);
}

// --------------------------------- launcher -------------------------------------
extern "C" void kernel_launch(void* const* d_in, const int* in_sizes, int n_in,
                              void* d_out, int out_size) {
    const float* cond  = (const float*)d_in[0];
    const float* w1    = (const float*)d_in[1];
    const float* b1    = (const float*)d_in[2];
    const float* w2    = (const float*)d_in[3];
    const float* b2    = (const float*)d_in[4];
    const float* w3    = (const float*)d_in[5];
    const float* b3    = (const float*)d_in[6];
    const float* r1w1  = (const float*)d_in[7];
    const float* r1b1  = (const float*)d_in[8];
    const float* r1w2  = (const float*)d_in[9];
    const float* r1b2  = (const float*)d_in[10];
    const float* r2w1  = (const float*)d_in[11];
    const float* r2b1  = (const float*)d_in[12];
    const float* r2w2  = (const float*)d_in[13];
    const float* r2b2  = (const float*)d_in[14];
    const float* wpre  = (const float*)d_in[15];
    const float* bpre  = (const float*)d_in[16];
    const float* cbk   = (const float*)d_in[17];

    float *h2p, *h3p, *h3rp, *tp, *w2tp, *w3tp, *wr1tp, *wr2tp;
    cudaGetSymbolAddress((void**)&h2p,   g_h2);
    cudaGetSymbolAddress((void**)&h3p,   g_h3);
    cudaGetSymbolAddress((void**)&h3rp,  g_h3r);
    cudaGetSymbolAddress((void**)&tp,    g_t);
    cudaGetSymbolAddress((void**)&w2tp,  g_w2t);
    cudaGetSymbolAddress((void**)&w3tp,  g_w3t);
    cudaGetSymbolAddress((void**)&wr1tp, g_wr1t);
    cudaGetSymbolAddress((void**)&wr2tp, g_wr2t);

    k_padw<<<1376, 256>>>(w2, w3, r1w1, r2w1);
    k_conv1<<<dim3(128, 16), 128>>>(cond, w1, b1);
    k_conv2<<<dim3(8, 8, 16), 128>>>(w2tp, b2);
    k_c3<true, true><<<dim3(4, 16, 16), 128>>>(h2p, w3tp, b3, h3p, h3rp, 128, 128, 128, 1);

    k_c3<false, false><<<dim3(4, 4, 32), 128>>>(h3rp, wr1tp, nullptr, tp, nullptr, 32, 128, 64, 2);
    k_res1x1_add<<<dim3(64, 2, 16), 64>>>(r1w2, r1b2, r1b1);

    k_c3<false, false><<<dim3(4, 4, 32), 128>>>(h3rp, wr2tp, nullptr, tp, nullptr, 32, 128, 64, 2);
    k_res1x1_add<<<dim3(64, 2, 16), 64>>>(r2w2, r2b2, r2b1);

    k_z<<<dim3(64, 16), 64>>>(wpre, bpre);
    k_vq<<<dim3(8, 16), 256>>>(cbk, (float*)d_out);
}

// round 7
// speedup vs baseline: 1.0358x; 1.0358x over previous
#include <cuda_runtime.h>
#include <cuda_pipeline.h>

typedef unsigned long long u64;

// ---- packed f32x2 helpers (exact IEEE fp32 per lane) ---------------------------
__device__ __forceinline__ u64 pk2(float lo, float hi) {
    u64 r; asm("mov.b64 %0, {%1, %2};" : "=l"(r) : "f"(lo), "f"(hi)); return r;
}
__device__ __forceinline__ void fma2(u64& d, u64 a, u64 b) {
    asm("fma.rn.f32x2 %0, %1, %2, %3;" : "=l"(d) : "l"(a), "l"(b), "l"(d));
}
__device__ __forceinline__ float2 up2(u64 v) {
    float lo, hi; asm("mov.b64 {%0, %1}, %2;" : "=f"(lo), "=f"(hi) : "l"(v));
    return make_float2(lo, hi);
}

// ---------------- scratch (static device globals; no allocation) ----------------
__device__ float g_h1 [16 * 64 * 128 * 128];
__device__ float g_h2 [16 * 128 * 64 * 64];
__device__ float g_h3 [16 * 128 * 64 * 64];
__device__ float g_h3r[16 * 128 * 64 * 64];
__device__ float g_t  [2 * 16 * 32 * 64 * 64];
__device__ float g_z  [16 * 4096 * 4];
// weights transposed to [ci][kh][kw][oc] (oc contiguous -> natural u64 oc-pairs)
__device__ float g_w2t [64 * 4 * 4 * 128];
__device__ float g_w3t [128 * 3 * 3 * 128];
__device__ float g_wr1t[128 * 3 * 3 * 32];
__device__ float g_wr2t[128 * 3 * 3 * 32];

// ------------- transpose weights to oc-innermost --------------------------------
__global__ void k_padw(const float* __restrict__ w2, const float* __restrict__ w3,
                       const float* __restrict__ r1, const float* __restrict__ r2) {
    const int i = blockIdx.x * 256 + threadIdx.x;
    if (i < 131072) {                      // conv2: [oc128][ci64][kh4][kw4]
        const int oc = i >> 10, r = i & 1023;          // r = ci*16 + kh*4 + kw
        g_w2t[r * 128 + oc] = w2[i];
    } else if (i < 131072 + 147456) {      // conv3: [oc128][ci128][9]
        const int j = i - 131072, oc = j / 1152, r = j % 1152;
        g_w3t[r * 128 + oc] = w3[j];
    } else if (i < 131072 + 147456 + 36864) {
        const int j = i - 131072 - 147456, oc = j / 1152, r = j % 1152;
        g_wr1t[r * 32 + oc] = r1[j];
    } else if (i < 131072 + 147456 + 73728) {
        const int j = i - 131072 - 147456 - 36864, oc = j / 1152, r = j % 1152;
        g_wr2t[r * 32 + oc] = r2[j];
    }
}

// ---------------- conv1: [16,1,256,256] -> relu -> [16,64,128,128], k4 s2 p1 ----
__global__ void k_conv1(const float* __restrict__ x, const float* __restrict__ w,
                        const float* __restrict__ b) {
    const int oy = blockIdx.x, bb = blockIdx.y, ox = threadIdx.x;
    __shared__ float sw[64 * 16];
    __shared__ float sb[64];
    for (int i = threadIdx.x; i < 64 * 16; i += 128) sw[i] = w[i];
    if (threadIdx.x < 64) sb[threadIdx.x] = b[threadIdx.x];
    __syncthreads();

    const float* xb = x + bb * 256 * 256;
    float iv[16];
#pragma unroll
    for (int kh = 0; kh < 4; kh++) {
        const int iy = 2 * oy - 1 + kh;
#pragma unroll
        for (int kw = 0; kw < 4; kw++) {
            const int ix = 2 * ox - 1 + kw;
            iv[kh * 4 + kw] = (iy >= 0 && iy < 256 && ix >= 0 && ix < 256)
                                  ? xb[iy * 256 + ix] : 0.f;
        }
    }
    float* ob = g_h1 + bb * 64 * 16384 + oy * 128 + ox;
    for (int oc = 0; oc < 64; oc++) {
        float a = sb[oc];
#pragma unroll
        for (int t = 0; t < 16; t++) a += iv[t] * sw[oc * 16 + t];
        ob[oc * 16384] = fmaxf(a, 0.f);
    }
}

// ---------------- conv2: k4 s2 p1, FFMA2 over oc pairs --------------------------
// block 128 = 16 xg (4px) x 8 rows; 16oc x 4px per thread
__global__ __launch_bounds__(128) void k_conv2(const float* __restrict__ wt,
                                               const float* __restrict__ b) {
    // grid (8 oy-tiles, 8 ocg, 16 batch)
    const int oy0 = blockIdx.x * 8, ocb = blockIdx.y * 16, bb = blockIdx.z;
    const int tid = threadIdx.x, txx = tid & 15, tyy = tid >> 4;

    __shared__ __align__(16) float s_in[2][2][18][136];  // interior [4..131]
    __shared__ __align__(16) float s_w [2][2][4][4][16]; // [ci][kh][kw][oc]

    for (int i = tid; i < 2 * 2 * 18; i += 128) {
        const int bf = i / 36, r = i % 36, ci = r / 18, row = r % 18;
        s_in[bf][ci][row][3]   = 0.f;
        s_in[bf][ci][row][132] = 0.f;
    }

    const float* inb = g_h1 + bb * 64 * 16384;

    auto stage = [&](int it, int bf) {
        const int c0 = it * 2;
        for (int i = tid; i < 1152; i += 128) {  // 2ci x 18row x 32 seg
            const int ci = i / 576, r = i % 576, row = r / 32, seg = r % 32;
            const int iy = 2 * oy0 - 1 + row;
            float* dst = &s_in[bf][ci][row][4 + seg * 4];
            if (iy >= 0 && iy < 128)
                __pipeline_memcpy_async(dst, inb + (c0 + ci) * 16384 + iy * 128 + seg * 4, 16);
            else
                *(float4*)dst = make_float4(0.f, 0.f, 0.f, 0.f);
        }
        for (int i = tid; i < 128; i += 128) {   // 2ci x 16 taps x 4 quads
            const int row = i >> 2, q = i & 3;   // row = ci*16 + kh*4 + kw
            __pipeline_memcpy_async(&((float*)s_w[bf])[row * 16 + q * 4],
                                    wt + (c0 * 16 + row) * 128 + ocb + q * 4, 16);
        }
    };

    u64 acc[8][4];  // [oc pair][px]
#pragma unroll
    for (int j = 0; j < 8; j++) {
        const u64 bv = pk2(b[ocb + 2 * j], b[ocb + 2 * j + 1]);
#pragma unroll
        for (int p = 0; p < 4; p++) acc[j][p] = bv;
    }

    stage(0, 0);
    __pipeline_commit();
    int cur = 0;
    for (int it = 0; it < 32; it++) {
        __pipeline_wait_prior(0);
        __syncthreads();
        if (it + 1 < 32) { stage(it + 1, cur ^ 1); __pipeline_commit(); }
#pragma unroll
        for (int ci = 0; ci < 2; ci++) {
#pragma unroll
            for (int kh = 0; kh < 4; kh++) {
                const float* rp = &s_in[cur][ci][2 * tyy + kh][8 * txx];
                const float4 A = *(const float4*)rp;
                const float4 B = *(const float4*)(rp + 4);
                const float4 C = *(const float4*)(rp + 8);
                const float  D = rp[12];
                u64 bv[10];
                bv[0] = pk2(A.w, A.w); bv[1] = pk2(B.x, B.x);
                bv[2] = pk2(B.y, B.y); bv[3] = pk2(B.z, B.z);
                bv[4] = pk2(B.w, B.w); bv[5] = pk2(C.x, C.x);
                bv[6] = pk2(C.y, C.y); bv[7] = pk2(C.z, C.z);
                bv[8] = pk2(C.w, C.w); bv[9] = pk2(D, D);
#pragma unroll
                for (int kw = 0; kw < 4; kw++) {
                    const u64* wb = (const u64*)&s_w[cur][ci][kh][kw][0];
                    const ulonglong2 W0 = *(const ulonglong2*)wb;
                    const ulonglong2 W1 = *(const ulonglong2*)(wb + 2);
                    const ulonglong2 W2 = *(const ulonglong2*)(wb + 4);
                    const ulonglong2 W3 = *(const ulonglong2*)(wb + 6);
                    const u64 w[8] = {W0.x, W0.y, W1.x, W1.y, W2.x, W2.y, W3.x, W3.y};
#pragma unroll
                    for (int j = 0; j < 8; j++)
#pragma unroll
                        for (int p = 0; p < 4; p++)
                            fma2(acc[j][p], bv[2 * p + kw], w[j]);
                }
            }
        }
        cur ^= 1;
    }
    float* ob = g_h2 + (bb * 128 + ocb) * 4096 + (oy0 + tyy) * 64 + 4 * txx;
#pragma unroll
    for (int j = 0; j < 8; j++) {
        const float2 f0 = up2(acc[j][0]), f1 = up2(acc[j][1]);
        const float2 f2 = up2(acc[j][2]), f3 = up2(acc[j][3]);
        *(float4*)(ob + (2 * j) * 4096) = make_float4(
            fmaxf(f0.x, 0.f), fmaxf(f1.x, 0.f), fmaxf(f2.x, 0.f), fmaxf(f3.x, 0.f));
        *(float4*)(ob + (2 * j + 1) * 4096) = make_float4(
            fmaxf(f0.y, 0.f), fmaxf(f1.y, 0.f), fmaxf(f2.y, 0.f), fmaxf(f3.y, 0.f));
    }
}

// ------- generic 3x3 s1 p1 conv on 64x64, FFMA2 over oc pairs (round-5 tile) ----
// block 128 = 16 xg (4px) x 8 rows; 16oc x 4px per thread
template <bool ADD_BIAS, bool WRITE_RELU>
__global__ __launch_bounds__(128) void k_c3(
    const float* __restrict__ in, const float* __restrict__ wt,
    const float* __restrict__ bias, float* __restrict__ out,
    float* __restrict__ outr, int COUT, int CIN_TOTAL, int CI_COUNT, int NSPLIT) {
    // grid (8 oy-tiles, COUT/16, 16*NSPLIT)
    const int oy0 = blockIdx.x * 8, ocb = blockIdx.y * 16;
    const int half = blockIdx.z % NSPLIT, bb = blockIdx.z / NSPLIT;
    const int ci0 = half * CI_COUNT;
    const int tid = threadIdx.x, txx = tid & 15, tyy = tid >> 4;

    __shared__ __align__(16) float s_in[2][4][10][72];    // interior [4..67]
    __shared__ __align__(16) float s_w [2][4][3][3][16];  // [ci][kh][kw][oc]

    for (int i = tid; i < 2 * 4 * 10; i += 128) {
        const int bf = i / 40, r = i % 40, ci = r / 10, row = r % 10;
        s_in[bf][ci][row][3]  = 0.f;
        s_in[bf][ci][row][68] = 0.f;
    }

    const float* inb = in + bb * CIN_TOTAL * 4096;

    auto stage = [&](int it, int bf) {
        const int c0 = ci0 + it * 4;
        for (int i = tid; i < 640; i += 128) {   // 4ci x 10row x 16 seg
            const int ci = i / 160, r = i % 160, row = r / 16, seg = r % 16;
            const int iy = oy0 - 1 + row;
            float* dst = &s_in[bf][ci][row][4 + seg * 4];
            if (iy >= 0 && iy < 64)
                __pipeline_memcpy_async(dst, inb + (c0 + ci) * 4096 + iy * 64 + seg * 4, 16);
            else
                *(float4*)dst = make_float4(0.f, 0.f, 0.f, 0.f);
        }
        for (int i = tid; i < 144; i += 128) {   // 4ci x 9 taps x 4 quads
            const int row = i >> 2, q = i & 3;   // row = ci*9 + kh*3 + kw
            __pipeline_memcpy_async(&((float*)s_w[bf])[row * 16 + q * 4],
                                    wt + (c0 * 9 + row) * COUT + ocb + q * 4, 16);
        }
    };

    u64 acc[8][4];
#pragma unroll
    for (int j = 0; j < 8; j++) {
        const float b0 = ADD_BIAS ? bias[ocb + 2 * j] : 0.f;
        const float b1 = ADD_BIAS ? bias[ocb + 2 * j + 1] : 0.f;
        const u64 bv = pk2(b0, b1);
#pragma unroll
        for (int p = 0; p < 4; p++) acc[j][p] = bv;
    }

    const int NITER = CI_COUNT / 4;
    stage(0, 0);
    __pipeline_commit();
    int cur = 0;
    for (int it = 0; it < NITER; it++) {
        __pipeline_wait_prior(0);
        __syncthreads();
        if (it + 1 < NITER) { stage(it + 1, cur ^ 1); __pipeline_commit(); }
#pragma unroll
        for (int ci = 0; ci < 4; ci++) {
#pragma unroll
            for (int kh = 0; kh < 3; kh++) {
                const float* rp = &s_in[cur][ci][tyy + kh][4 * txx];
                const float4 A = *(const float4*)rp;
                const float4 B = *(const float4*)(rp + 4);
                const float  E = rp[8];
                u64 bv[6];
                bv[0] = pk2(A.w, A.w); bv[1] = pk2(B.x, B.x);
                bv[2] = pk2(B.y, B.y); bv[3] = pk2(B.z, B.z);
                bv[4] = pk2(B.w, B.w); bv[5] = pk2(E, E);
#pragma unroll
                for (int kw = 0; kw < 3; kw++) {
                    const u64* wb = (const u64*)&s_w[cur][ci][kh][kw][0];
                    const ulonglong2 W0 = *(const ulonglong2*)wb;
                    const ulonglong2 W1 = *(const ulonglong2*)(wb + 2);
                    const ulonglong2 W2 = *(const ulonglong2*)(wb + 4);
                    const ulonglong2 W3 = *(const ulonglong2*)(wb + 6);
                    const u64 w[8] = {W0.x, W0.y, W1.x, W1.y, W2.x, W2.y, W3.x, W3.y};
#pragma unroll
                    for (int j = 0; j < 8; j++)
#pragma unroll
                        for (int p = 0; p < 4; p++)
                            fma2(acc[j][p], bv[p + kw], w[j]);
                }
            }
        }
        cur ^= 1;
    }
    const int off = ((half * 16 + bb) * COUT + ocb) * 4096 + (oy0 + tyy) * 64 + 4 * txx;
#pragma unroll
    for (int j = 0; j < 8; j++) {
        const float2 f0 = up2(acc[j][0]), f1 = up2(acc[j][1]);
        const float2 f2 = up2(acc[j][2]), f3 = up2(acc[j][3]);
        const float4 v0 = make_float4(f0.x, f1.x, f2.x, f3.x);
        const float4 v1 = make_float4(f0.y, f1.y, f2.y, f3.y);
        *(float4*)(out + off + (2 * j) * 4096) = v0;
        *(float4*)(out + off + (2 * j + 1) * 4096) = v1;
        if (WRITE_RELU) {
            *(float4*)(outr + off + (2 * j) * 4096) = make_float4(
                fmaxf(v0.x, 0.f), fmaxf(v0.y, 0.f), fmaxf(v0.z, 0.f), fmaxf(v0.w, 0.f));
            *(float4*)(outr + off + (2 * j + 1) * 4096) = make_float4(
                fmaxf(v1.x, 0.f), fmaxf(v1.y, 0.f), fmaxf(v1.z, 0.f), fmaxf(v1.w, 0.f));
        }
    }
}

// ------- residual 1x1 (FFMA2 oc-pairs): h3 += b + W*relu(t0+t1+bt); h3r=relu ----
__global__ __launch_bounds__(64) void k_res1x1_add(const float* __restrict__ w,
                                                   const float* __restrict__ b,
                                                   const float* __restrict__ bt) {
    // grid (xyg=64, ocg=2, b=16), block 64 (one px per thread, 64 oc)
    const int xy0 = blockIdx.x * 64, ocb = blockIdx.y * 64, bb = blockIdx.z, tx = threadIdx.x;
    __shared__ float s_t[32][64];
    __shared__ __align__(16) float s_w[32][64];   // [ci][oc] -> u64 oc-pairs

    const float* t0 = g_t + bb * 32 * 4096 + xy0;
    const float* t1 = g_t + (16 + bb) * 32 * 4096 + xy0;
    for (int i = tx; i < 32 * 64; i += 64) {
        const int ci = i / 64, xx = i % 64;
        s_t[ci][xx] = fmaxf(t0[ci * 4096 + xx] + t1[ci * 4096 + xx] + bt[ci], 0.f);
    }
    for (int i = tx; i < 64 * 32; i += 64) {
        const int o = i / 32, ci = i % 32;
        s_w[ci][o] = w[(ocb + o) * 32 + ci];
    }
    __syncthreads();

    u64 acc[32];
#pragma unroll
    for (int j = 0; j < 32; j++) acc[j] = pk2(b[ocb + 2 * j], b[ocb + 2 * j + 1]);

#pragma unroll 4
    for (int ci = 0; ci < 32; ci++) {
        const float v = s_t[ci][tx];
        const u64 vv = pk2(v, v);
        const u64* wr = (const u64*)&s_w[ci][0];
#pragma unroll
        for (int j = 0; j < 32; j++) fma2(acc[j], vv, wr[j]);
    }

    float* hb  = g_h3  + (bb * 128 + ocb) * 4096 + xy0 + tx;
    float* hrb = g_h3r + (bb * 128 + ocb) * 4096 + xy0 + tx;
#pragma unroll
    for (int j = 0; j < 32; j++) {
        const float2 f = up2(acc[j]);
        const float h0 = hb[(2 * j) * 4096] + f.x;
        const float h1 = hb[(2 * j + 1) * 4096] + f.y;
        hb[(2 * j) * 4096]      = h0;
        hb[(2 * j + 1) * 4096]  = h1;
        hrb[(2 * j) * 4096]     = fmaxf(h0, 0.f);
        hrb[(2 * j + 1) * 4096] = fmaxf(h1, 0.f);
    }
}

// ------- pre-VQ 1x1 (FFMA2): z[pos][4] = W(128->4) * h3r + bias -----------------
__global__ void k_z(const float* __restrict__ w, const float* __restrict__ b) {
    const int xy0 = blockIdx.x * 64, bb = blockIdx.y, tx = threadIdx.x;
    __shared__ float s_h[128][64];
    __shared__ __align__(16) float s_w[128][4];   // [ci][oc4] -> u64 pairs

    const float* hb = g_h3r + bb * 128 * 4096 + xy0;
    for (int i = tx; i < 128 * 64; i += 64) {
        const int ci = i / 64, xx = i % 64;
        s_h[ci][xx] = hb[ci * 4096 + xx];
    }
    for (int i = tx; i < 512; i += 64) s_w[i & 127][i >> 7] = w[(i >> 7) * 128 + (i & 127)];
    __syncthreads();

    u64 a01 = pk2(b[0], b[1]), a23 = pk2(b[2], b[3]);
#pragma unroll 8
    for (int ci = 0; ci < 128; ci++) {
        const float hv = s_h[ci][tx];
        const u64 vv = pk2(hv, hv);
        const u64* wr = (const u64*)&s_w[ci][0];
        fma2(a01, vv, wr[0]);
        fma2(a23, vv, wr[1]);
    }
    const float2 f01 = up2(a01), f23 = up2(a23);
    ((float4*)g_z)[bb * 4096 + xy0 + tx] = make_float4(f01.x, f01.y, f23.x, f23.y);
}

// ------- cosine VQ: argmax_k <z, e_k/||e_k||>, gather codebook ------------------
__global__ void k_vq(const float* __restrict__ cb, float* __restrict__ out) {
    const int bb = blockIdx.y;
    const int p0 = (blockIdx.x * 256 + threadIdx.x) * 2;
    __shared__ float4 s_en[2048];
    for (int k = threadIdx.x; k < 2048; k += 256) {
        const float4 c = ((const float4*)cb)[k];
        const float n = sqrtf(c.x * c.x + c.y * c.y + c.z * c.z + c.w * c.w);
        const float inv = 1.f / (n + 1e-12f);
        s_en[k] = make_float4(c.x * inv, c.y * inv, c.z * inv, c.w * inv);
    }
    __syncthreads();

    float4 z[2];
#pragma unroll
    for (int q = 0; q < 2; q++) z[q] = ((const float4*)g_z)[bb * 4096 + p0 + q];

    float best[2] = {-1e30f, -1e30f};
    int bi[2] = {0, 0};
#pragma unroll 4
    for (int k = 0; k < 2048; k++) {
        const float4 e = s_en[k];
#pragma unroll
        for (int q = 0; q < 2; q++) {
            const float s = z[q].x * e.x + z[q].y * e.y + z[q].z * e.z + z[q].w * e.w;
            if (s > best[q]) { best[q] = s; bi[q] = k; }  // strict >: first max (JAX)
        }
    }
    const float4 q0 = ((const float4*)cb)[bi[0]];
    const float4 q1 = ((const float4*)cb)[bi[1]];
    float* ob = out + bb * 4 * 4096 + p0;
    *(float2*)(ob)            = make_float2(q0.x, q1.x);
    *(float2*)(ob + 4096)     = make_float2(q0.y, q1.y);
    *(float2*)(ob + 2 * 4096) = make_float2(q0.z, q1.z);
    *(float2*)(ob + 3 * 4096) = make_float2(q0.w, q1.w);
}

// --------------------------------- launcher -------------------------------------
extern "C" void kernel_launch(void* const* d_in, const int* in_sizes, int n_in,
                              void* d_out, int out_size) {
    const float* cond  = (const float*)d_in[0];
    const float* w1    = (const float*)d_in[1];
    const float* b1    = (const float*)d_in[2];
    const float* w2    = (const float*)d_in[3];
    const float* b2    = (const float*)d_in[4];
    const float* w3    = (const float*)d_in[5];
    const float* b3    = (const float*)d_in[6];
    const float* r1w1  = (const float*)d_in[7];
    const float* r1b1  = (const float*)d_in[8];
    const float* r1w2  = (const float*)d_in[9];
    const float* r1b2  = (const float*)d_in[10];
    const float* r2w1  = (const float*)d_in[11];
    const float* r2b1  = (const float*)d_in[12];
    const float* r2w2  = (const float*)d_in[13];
    const float* r2b2  = (const float*)d_in[14];
    const float* wpre  = (const float*)d_in[15];
    const float* bpre  = (const float*)d_in[16];
    const float* cbk   = (const float*)d_in[17];

    float *h2p, *h3p, *h3rp, *tp, *w2tp, *w3tp, *wr1tp, *wr2tp;
    cudaGetSymbolAddress((void**)&h2p,   g_h2);
    cudaGetSymbolAddress((void**)&h3p,   g_h3);
    cudaGetSymbolAddress((void**)&h3rp,  g_h3r);
    cudaGetSymbolAddress((void**)&tp,    g_t);
    cudaGetSymbolAddress((void**)&w2tp,  g_w2t);
    cudaGetSymbolAddress((void**)&w3tp,  g_w3t);
    cudaGetSymbolAddress((void**)&wr1tp, g_wr1t);
    cudaGetSymbolAddress((void**)&wr2tp, g_wr2t);

    k_padw<<<1376, 256>>>(w2, w3, r1w1, r2w1);
    k_conv1<<<dim3(128, 16), 128>>>(cond, w1, b1);
    k_conv2<<<dim3(8, 8, 16), 128>>>(w2tp, b2);
    k_c3<true, true><<<dim3(8, 8, 16), 128>>>(h2p, w3tp, b3, h3p, h3rp, 128, 128, 128, 1);

    k_c3<false, false><<<dim3(8, 2, 32), 128>>>(h3rp, wr1tp, nullptr, tp, nullptr, 32, 128, 64, 2);
    k_res1x1_add<<<dim3(64, 2, 16), 64>>>(r1w2, r1b2, r1b1);

    k_c3<false, false><<<dim3(8, 2, 32), 128>>>(h3rp, wr2tp, nullptr, tp, nullptr, 32, 128, 64, 2);
    k_res1x1_add<<<dim3(64, 2, 16), 64>>>(r2w2, r2b2, r2b1);

    k_z<<<dim3(64, 16), 64>>>(wpre, bpre);
    k_vq<<<dim3(8, 16), 256>>>(cbk, (float*)d_out);
}

// round 8
// speedup vs baseline: 1.0759x; 1.0388x over previous
#include <cuda_runtime.h>
#include <cuda_pipeline.h>

typedef unsigned long long u64;

// ---- packed f32x2 helpers (exact IEEE fp32 per lane) ---------------------------
__device__ __forceinline__ u64 pk2(float lo, float hi) {
    u64 r; asm("mov.b64 %0, {%1, %2};" : "=l"(r) : "f"(lo), "f"(hi)); return r;
}
__device__ __forceinline__ void fma2(u64& d, u64 a, u64 b) {
    asm("fma.rn.f32x2 %0, %1, %2, %3;" : "=l"(d) : "l"(a), "l"(b), "l"(d));
}
__device__ __forceinline__ float2 up2(u64 v) {
    float lo, hi; asm("mov.b64 {%0, %1}, %2;" : "=f"(lo), "=f"(hi) : "l"(v));
    return make_float2(lo, hi);
}

// ---------------- scratch (static device globals; no allocation) ----------------
__device__ float g_h1 [16 * 64 * 128 * 128];
__device__ float g_h2 [16 * 128 * 64 * 64];
__device__ float g_h3 [16 * 128 * 64 * 64];
__device__ float g_h3r[16 * 128 * 64 * 64];
__device__ float g_t  [2 * 16 * 32 * 64 * 64];
__device__ float g_z  [16 * 4096 * 4];
// weights transposed to [ci][kh][kw][oc] (oc contiguous -> natural u64 oc-pairs)
__device__ float g_w2t [64 * 4 * 4 * 128];
__device__ float g_w3t [128 * 3 * 3 * 128];
__device__ float g_wr1t[128 * 3 * 3 * 32];
__device__ float g_wr2t[128 * 3 * 3 * 32];
__device__ float g_w1t [16 * 64];             // conv1: [tap][oc]

// ------------- transpose weights to oc-innermost --------------------------------
__global__ void k_padw(const float* __restrict__ w2, const float* __restrict__ w3,
                       const float* __restrict__ r1, const float* __restrict__ r2,
                       const float* __restrict__ w1) {
    const int i = blockIdx.x * 256 + threadIdx.x;
    if (i < 131072) {                      // conv2: [oc128][ci64][kh4][kw4]
        const int oc = i >> 10, r = i & 1023;          // r = ci*16 + kh*4 + kw
        g_w2t[r * 128 + oc] = w2[i];
    } else if (i < 131072 + 147456) {      // conv3: [oc128][ci128][9]
        const int j = i - 131072, oc = j / 1152, r = j % 1152;
        g_w3t[r * 128 + oc] = w3[j];
    } else if (i < 131072 + 147456 + 36864) {
        const int j = i - 131072 - 147456, oc = j / 1152, r = j % 1152;
        g_wr1t[r * 32 + oc] = r1[j];
    } else if (i < 131072 + 147456 + 73728) {
        const int j = i - 131072 - 147456 - 36864, oc = j / 1152, r = j % 1152;
        g_wr2t[r * 32 + oc] = r2[j];
    } else if (i < 131072 + 147456 + 73728 + 1024) {
        const int j = i - 131072 - 147456 - 73728, oc = j >> 4, r = j & 15;
        g_w1t[r * 64 + oc] = w1[j];
    }
}

// ------- conv1 (FFMA2 oc-pairs): [16,1,256,256] -> relu -> [16,64,128,128] ------
__global__ void k_conv1(const float* __restrict__ x, const float* __restrict__ wt,
                        const float* __restrict__ b) {
    const int oy = blockIdx.x, bb = blockIdx.y, ox = threadIdx.x;
    __shared__ __align__(16) float sw[16][64];   // [tap][oc]
    __shared__ float sb[64];
    for (int i = threadIdx.x; i < 1024; i += 128) sw[i >> 6][i & 63] = wt[i];
    if (threadIdx.x < 64) sb[threadIdx.x] = b[threadIdx.x];
    __syncthreads();

    const float* xb = x + bb * 256 * 256;
    float iv[16];
#pragma unroll
    for (int kh = 0; kh < 4; kh++) {
        const int iy = 2 * oy - 1 + kh;
#pragma unroll
        for (int kw = 0; kw < 4; kw++) {
            const int ix = 2 * ox - 1 + kw;
            iv[kh * 4 + kw] = (iy >= 0 && iy < 256 && ix >= 0 && ix < 256)
                                  ? xb[iy * 256 + ix] : 0.f;
        }
    }
    u64 acc[32];
#pragma unroll
    for (int j = 0; j < 32; j++) acc[j] = pk2(sb[2 * j], sb[2 * j + 1]);
#pragma unroll
    for (int t = 0; t < 16; t++) {
        const u64 vv = pk2(iv[t], iv[t]);
        const u64* wr = (const u64*)&sw[t][0];
#pragma unroll
        for (int j = 0; j < 32; j++) fma2(acc[j], vv, wr[j]);
    }
    float* ob = g_h1 + bb * 64 * 16384 + oy * 128 + ox;
#pragma unroll
    for (int j = 0; j < 32; j++) {
        const float2 f = up2(acc[j]);
        ob[(2 * j) * 16384]     = fmaxf(f.x, 0.f);
        ob[(2 * j + 1) * 16384] = fmaxf(f.y, 0.f);
    }
}

// ---------------- conv2: k4 s2 p1, FFMA2 over oc pairs --------------------------
// block 128 = 16 xg (4px) x 8 rows; 16oc x 4px per thread
__global__ __launch_bounds__(128) void k_conv2(const float* __restrict__ wt,
                                               const float* __restrict__ b) {
    // grid (8 oy-tiles, 8 ocg, 16 batch)
    const int oy0 = blockIdx.x * 8, ocb = blockIdx.y * 16, bb = blockIdx.z;
    const int tid = threadIdx.x, txx = tid & 15, tyy = tid >> 4;

    __shared__ __align__(16) float s_in[2][2][18][136];  // interior [4..131]
    __shared__ __align__(16) float s_w [2][2][4][4][16]; // [ci][kh][kw][oc]

    for (int i = tid; i < 2 * 2 * 18; i += 128) {
        const int bf = i / 36, r = i % 36, ci = r / 18, row = r % 18;
        s_in[bf][ci][row][3]   = 0.f;
        s_in[bf][ci][row][132] = 0.f;
    }

    const float* inb = g_h1 + bb * 64 * 16384;

    auto stage = [&](int it, int bf) {
        const int c0 = it * 2;
        for (int i = tid; i < 1152; i += 128) {  // 2ci x 18row x 32 seg
            const int ci = i / 576, r = i % 576, row = r / 32, seg = r % 32;
            const int iy = 2 * oy0 - 1 + row;
            float* dst = &s_in[bf][ci][row][4 + seg * 4];
            if (iy >= 0 && iy < 128)
                __pipeline_memcpy_async(dst, inb + (c0 + ci) * 16384 + iy * 128 + seg * 4, 16);
            else
                *(float4*)dst = make_float4(0.f, 0.f, 0.f, 0.f);
        }
        for (int i = tid; i < 128; i += 128) {   // 2ci x 16 taps x 4 quads
            const int row = i >> 2, q = i & 3;   // row = ci*16 + kh*4 + kw
            __pipeline_memcpy_async(&((float*)s_w[bf])[row * 16 + q * 4],
                                    wt + (c0 * 16 + row) * 128 + ocb + q * 4, 16);
        }
    };

    u64 acc[8][4];  // [oc pair][px]
#pragma unroll
    for (int j = 0; j < 8; j++) {
        const u64 bv = pk2(b[ocb + 2 * j], b[ocb + 2 * j + 1]);
#pragma unroll
        for (int p = 0; p < 4; p++) acc[j][p] = bv;
    }

    stage(0, 0);
    __pipeline_commit();
    int cur = 0;
    for (int it = 0; it < 32; it++) {
        __pipeline_wait_prior(0);
        __syncthreads();
        if (it + 1 < 32) { stage(it + 1, cur ^ 1); __pipeline_commit(); }
#pragma unroll
        for (int ci = 0; ci < 2; ci++) {
#pragma unroll
            for (int kh = 0; kh < 4; kh++) {
                const float* rp = &s_in[cur][ci][2 * tyy + kh][8 * txx];
                const float4 A = *(const float4*)rp;
                const float4 B = *(const float4*)(rp + 4);
                const float4 C = *(const float4*)(rp + 8);
                const float  D = rp[12];
                u64 bv[10];
                bv[0] = pk2(A.w, A.w); bv[1] = pk2(B.x, B.x);
                bv[2] = pk2(B.y, B.y); bv[3] = pk2(B.z, B.z);
                bv[4] = pk2(B.w, B.w); bv[5] = pk2(C.x, C.x);
                bv[6] = pk2(C.y, C.y); bv[7] = pk2(C.z, C.z);
                bv[8] = pk2(C.w, C.w); bv[9] = pk2(D, D);
#pragma unroll
                for (int kw = 0; kw < 4; kw++) {
                    const u64* wb = (const u64*)&s_w[cur][ci][kh][kw][0];
                    const ulonglong2 W0 = *(const ulonglong2*)wb;
                    const ulonglong2 W1 = *(const ulonglong2*)(wb + 2);
                    const ulonglong2 W2 = *(const ulonglong2*)(wb + 4);
                    const ulonglong2 W3 = *(const ulonglong2*)(wb + 6);
                    const u64 w[8] = {W0.x, W0.y, W1.x, W1.y, W2.x, W2.y, W3.x, W3.y};
#pragma unroll
                    for (int j = 0; j < 8; j++)
#pragma unroll
                        for (int p = 0; p < 4; p++)
                            fma2(acc[j][p], bv[2 * p + kw], w[j]);
                }
            }
        }
        cur ^= 1;
    }
    float* ob = g_h2 + (bb * 128 + ocb) * 4096 + (oy0 + tyy) * 64 + 4 * txx;
#pragma unroll
    for (int j = 0; j < 8; j++) {
        const float2 f0 = up2(acc[j][0]), f1 = up2(acc[j][1]);
        const float2 f2 = up2(acc[j][2]), f3 = up2(acc[j][3]);
        *(float4*)(ob + (2 * j) * 4096) = make_float4(
            fmaxf(f0.x, 0.f), fmaxf(f1.x, 0.f), fmaxf(f2.x, 0.f), fmaxf(f3.x, 0.f));
        *(float4*)(ob + (2 * j + 1) * 4096) = make_float4(
            fmaxf(f0.y, 0.f), fmaxf(f1.y, 0.f), fmaxf(f2.y, 0.f), fmaxf(f3.y, 0.f));
    }
}

// ------- generic 3x3 s1 p1 conv on 64x64, FFMA2 over oc pairs (round-5 tile) ----
// block 128 = 16 xg (4px) x 8 rows; 16oc x 4px per thread
template <bool ADD_BIAS, bool WRITE_RELU>
__global__ __launch_bounds__(128) void k_c3(
    const float* __restrict__ in, const float* __restrict__ wt,
    const float* __restrict__ bias, float* __restrict__ out,
    float* __restrict__ outr, int COUT, int CIN_TOTAL, int CI_COUNT, int NSPLIT) {
    // grid (8 oy-tiles, COUT/16, 16*NSPLIT)
    const int oy0 = blockIdx.x * 8, ocb = blockIdx.y * 16;
    const int half = blockIdx.z % NSPLIT, bb = blockIdx.z / NSPLIT;
    const int ci0 = half * CI_COUNT;
    const int tid = threadIdx.x, txx = tid & 15, tyy = tid >> 4;

    __shared__ __align__(16) float s_in[2][4][10][72];    // interior [4..67]
    __shared__ __align__(16) float s_w [2][4][3][3][16];  // [ci][kh][kw][oc]

    for (int i = tid; i < 2 * 4 * 10; i += 128) {
        const int bf = i / 40, r = i % 40, ci = r / 10, row = r % 10;
        s_in[bf][ci][row][3]  = 0.f;
        s_in[bf][ci][row][68] = 0.f;
    }

    const float* inb = in + bb * CIN_TOTAL * 4096;

    auto stage = [&](int it, int bf) {
        const int c0 = ci0 + it * 4;
        for (int i = tid; i < 640; i += 128) {   // 4ci x 10row x 16 seg
            const int ci = i / 160, r = i % 160, row = r / 16, seg = r % 16;
            const int iy = oy0 - 1 + row;
            float* dst = &s_in[bf][ci][row][4 + seg * 4];
            if (iy >= 0 && iy < 64)
                __pipeline_memcpy_async(dst, inb + (c0 + ci) * 4096 + iy * 64 + seg * 4, 16);
            else
                *(float4*)dst = make_float4(0.f, 0.f, 0.f, 0.f);
        }
        for (int i = tid; i < 144; i += 128) {   // 4ci x 9 taps x 4 quads
            const int row = i >> 2, q = i & 3;   // row = ci*9 + kh*3 + kw
            __pipeline_memcpy_async(&((float*)s_w[bf])[row * 16 + q * 4],
                                    wt + (c0 * 9 + row) * COUT + ocb + q * 4, 16);
        }
    };

    u64 acc[8][4];
#pragma unroll
    for (int j = 0; j < 8; j++) {
        const float b0 = ADD_BIAS ? bias[ocb + 2 * j] : 0.f;
        const float b1 = ADD_BIAS ? bias[ocb + 2 * j + 1] : 0.f;
        const u64 bv = pk2(b0, b1);
#pragma unroll
        for (int p = 0; p < 4; p++) acc[j][p] = bv;
    }

    const int NITER = CI_COUNT / 4;
    stage(0, 0);
    __pipeline_commit();
    int cur = 0;
    for (int it = 0; it < NITER; it++) {
        __pipeline_wait_prior(0);
        __syncthreads();
        if (it + 1 < NITER) { stage(it + 1, cur ^ 1); __pipeline_commit(); }
#pragma unroll
        for (int ci = 0; ci < 4; ci++) {
#pragma unroll
            for (int kh = 0; kh < 3; kh++) {
                const float* rp = &s_in[cur][ci][tyy + kh][4 * txx];
                const float4 A = *(const float4*)rp;
                const float4 B = *(const float4*)(rp + 4);
                const float  E = rp[8];
                u64 bv[6];
                bv[0] = pk2(A.w, A.w); bv[1] = pk2(B.x, B.x);
                bv[2] = pk2(B.y, B.y); bv[3] = pk2(B.z, B.z);
                bv[4] = pk2(B.w, B.w); bv[5] = pk2(E, E);
#pragma unroll
                for (int kw = 0; kw < 3; kw++) {
                    const u64* wb = (const u64*)&s_w[cur][ci][kh][kw][0];
                    const ulonglong2 W0 = *(const ulonglong2*)wb;
                    const ulonglong2 W1 = *(const ulonglong2*)(wb + 2);
                    const ulonglong2 W2 = *(const ulonglong2*)(wb + 4);
                    const ulonglong2 W3 = *(const ulonglong2*)(wb + 6);
                    const u64 w[8] = {W0.x, W0.y, W1.x, W1.y, W2.x, W2.y, W3.x, W3.y};
#pragma unroll
                    for (int j = 0; j < 8; j++)
#pragma unroll
                        for (int p = 0; p < 4; p++)
                            fma2(acc[j][p], bv[p + kw], w[j]);
                }
            }
        }
        cur ^= 1;
    }
    const int off = ((half * 16 + bb) * COUT + ocb) * 4096 + (oy0 + tyy) * 64 + 4 * txx;
#pragma unroll
    for (int j = 0; j < 8; j++) {
        const float2 f0 = up2(acc[j][0]), f1 = up2(acc[j][1]);
        const float2 f2 = up2(acc[j][2]), f3 = up2(acc[j][3]);
        const float4 v0 = make_float4(f0.x, f1.x, f2.x, f3.x);
        const float4 v1 = make_float4(f0.y, f1.y, f2.y, f3.y);
        *(float4*)(out + off + (2 * j) * 4096) = v0;
        *(float4*)(out + off + (2 * j + 1) * 4096) = v1;
        if (WRITE_RELU) {
            *(float4*)(outr + off + (2 * j) * 4096) = make_float4(
                fmaxf(v0.x, 0.f), fmaxf(v0.y, 0.f), fmaxf(v0.z, 0.f), fmaxf(v0.w, 0.f));
            *(float4*)(outr + off + (2 * j + 1) * 4096) = make_float4(
                fmaxf(v1.x, 0.f), fmaxf(v1.y, 0.f), fmaxf(v1.z, 0.f), fmaxf(v1.w, 0.f));
        }
    }
}

// ------- residual 1x1 #1 (FFMA2): h3 += b + W*relu(t0+t1+bt); h3r = relu --------
__global__ __launch_bounds__(64) void k_res1x1_add(const float* __restrict__ w,
                                                   const float* __restrict__ b,
                                                   const float* __restrict__ bt) {
    // grid (xyg=64, ocg=2, b=16), block 64 (one px per thread, 64 oc)
    const int xy0 = blockIdx.x * 64, ocb = blockIdx.y * 64, bb = blockIdx.z, tx = threadIdx.x;
    __shared__ float s_t[32][64];
    __shared__ __align__(16) float s_w[32][64];   // [ci][oc] -> u64 oc-pairs

    const float* t0 = g_t + bb * 32 * 4096 + xy0;
    const float* t1 = g_t + (16 + bb) * 32 * 4096 + xy0;
    for (int i = tx; i < 32 * 64; i += 64) {
        const int ci = i / 64, xx = i % 64;
        s_t[ci][xx] = fmaxf(t0[ci * 4096 + xx] + t1[ci * 4096 + xx] + bt[ci], 0.f);
    }
    for (int i = tx; i < 64 * 32; i += 64) {
        const int o = i / 32, ci = i % 32;
        s_w[ci][o] = w[(ocb + o) * 32 + ci];
    }
    __syncthreads();

    u64 acc[32];
#pragma unroll
    for (int j = 0; j < 32; j++) acc[j] = pk2(b[ocb + 2 * j], b[ocb + 2 * j + 1]);

#pragma unroll 4
    for (int ci = 0; ci < 32; ci++) {
        const float v = s_t[ci][tx];
        const u64 vv = pk2(v, v);
        const u64* wr = (const u64*)&s_w[ci][0];
#pragma unroll
        for (int j = 0; j < 32; j++) fma2(acc[j], vv, wr[j]);
    }

    float* hb  = g_h3  + (bb * 128 + ocb) * 4096 + xy0 + tx;
    float* hrb = g_h3r + (bb * 128 + ocb) * 4096 + xy0 + tx;
#pragma unroll
    for (int j = 0; j < 32; j++) {
        const float2 f = up2(acc[j]);
        const float h0 = hb[(2 * j) * 4096] + f.x;
        const float h1 = hb[(2 * j + 1) * 4096] + f.y;
        hb[(2 * j) * 4096]      = h0;
        hb[(2 * j + 1) * 4096]  = h1;
        hrb[(2 * j) * 4096]     = fmaxf(h0, 0.f);
        hrb[(2 * j + 1) * 4096] = fmaxf(h1, 0.f);
    }
}

// ------- fused res-block-2 1x1 + pre-VQ: z = Wz*relu(h3 + b + W*relu(t)) + bz ---
__global__ __launch_bounds__(64) void k_res1x1z(const float* __restrict__ w,
                                                const float* __restrict__ b,
                                                const float* __restrict__ bt,
                                                const float* __restrict__ wz,
                                                const float* __restrict__ bz) {
    // grid (xyg=64, b=16), block 64: one px per thread, ALL 128 oc
    const int xy0 = blockIdx.x * 64, bb = blockIdx.y, tx = threadIdx.x;
    __shared__ float s_t[32][64];
    __shared__ __align__(16) float s_w [32][128];  // [ci][oc]
    __shared__ __align__(16) float s_wz[128][4];   // [ci][oc4]

    const float* t0 = g_t + bb * 32 * 4096 + xy0;
    const float* t1 = g_t + (16 + bb) * 32 * 4096 + xy0;
    for (int i = tx; i < 32 * 64; i += 64) {
        const int ci = i / 64, xx = i % 64;
        s_t[ci][xx] = fmaxf(t0[ci * 4096 + xx] + t1[ci * 4096 + xx] + bt[ci], 0.f);
    }
    for (int i = tx; i < 128 * 32; i += 64) {
        const int o = i / 32, ci = i % 32;
        s_w[ci][o] = w[o * 32 + ci];
    }
    for (int i = tx; i < 512; i += 64) s_wz[i & 127][i >> 7] = wz[(i >> 7) * 128 + (i & 127)];
    __syncthreads();

    u64 acc[64];
#pragma unroll
    for (int j = 0; j < 64; j++) acc[j] = pk2(b[2 * j], b[2 * j + 1]);

#pragma unroll 4
    for (int ci = 0; ci < 32; ci++) {
        const float v = s_t[ci][tx];
        const u64 vv = pk2(v, v);
        const u64* wr = (const u64*)&s_w[ci][0];
#pragma unroll
        for (int j = 0; j < 64; j++) fma2(acc[j], vv, wr[j]);
    }

    // h = h3 + acc (raw h3 from res-block 1); z = Wz * relu(h) + bz, ci ascending
    const float* hb = g_h3 + bb * 128 * 4096 + xy0 + tx;
    u64 a01 = pk2(bz[0], bz[1]), a23 = pk2(bz[2], bz[3]);
#pragma unroll
    for (int j = 0; j < 64; j++) {
        const float2 f = up2(acc[j]);
        const float h0 = fmaxf(hb[(2 * j) * 4096] + f.x, 0.f);
        const float h1 = fmaxf(hb[(2 * j + 1) * 4096] + f.y, 0.f);
        const u64* wr0 = (const u64*)&s_wz[2 * j][0];
        const u64* wr1 = (const u64*)&s_wz[2 * j + 1][0];
        const u64 v0 = pk2(h0, h0), v1 = pk2(h1, h1);
        fma2(a01, v0, wr0[0]); fma2(a23, v0, wr0[1]);
        fma2(a01, v1, wr1[0]); fma2(a23, v1, wr1[1]);
    }
    const float2 f01 = up2(a01), f23 = up2(a23);
    ((float4*)g_z)[bb * 4096 + xy0 + tx] = make_float4(f01.x, f01.y, f23.x, f23.y);
}

// ------- cosine VQ: argmax_k <z, e_k/||e_k||>, gather codebook ------------------
__global__ void k_vq(const float* __restrict__ cb, float* __restrict__ out) {
    const int bb = blockIdx.y;
    const int p0 = (blockIdx.x * 256 + threadIdx.x) * 2;
    __shared__ float4 s_en[2048];
    for (int k = threadIdx.x; k < 2048; k += 256) {
        const float4 c = ((const float4*)cb)[k];
        const float n = sqrtf(c.x * c.x + c.y * c.y + c.z * c.z + c.w * c.w);
        const float inv = 1.f / (n + 1e-12f);
        s_en[k] = make_float4(c.x * inv, c.y * inv, c.z * inv, c.w * inv);
    }
    __syncthreads();

    float4 z[2];
#pragma unroll
    for (int q = 0; q < 2; q++) z[q] = ((const float4*)g_z)[bb * 4096 + p0 + q];

    float best[2] = {-1e30f, -1e30f};
    int bi[2] = {0, 0};
#pragma unroll 4
    for (int k = 0; k < 2048; k++) {
        const float4 e = s_en[k];
#pragma unroll
        for (int q = 0; q < 2; q++) {
            const float s = z[q].x * e.x + z[q].y * e.y + z[q].z * e.z + z[q].w * e.w;
            if (s > best[q]) { best[q] = s; bi[q] = k; }  // strict >: first max (JAX)
        }
    }
    const float4 q0 = ((const float4*)cb)[bi[0]];
    const float4 q1 = ((const float4*)cb)[bi[1]];
    float* ob = out + bb * 4 * 4096 + p0;
    *(float2*)(ob)            = make_float2(q0.x, q1.x);
    *(float2*)(ob + 4096)     = make_float2(q0.y, q1.y);
    *(float2*)(ob + 2 * 4096) = make_float2(q0.z, q1.z);
    *(float2*)(ob + 3 * 4096) = make_float2(q0.w, q1.w);
}

// --------------------------------- launcher -------------------------------------
extern "C" void kernel_launch(void* const* d_in, const int* in_sizes, int n_in,
                              void* d_out, int out_size) {
    const float* cond  = (const float*)d_in[0];
    const float* w1    = (const float*)d_in[1];
    const float* b1    = (const float*)d_in[2];
    const float* w2    = (const float*)d_in[3];
    const float* b2    = (const float*)d_in[4];
    const float* w3    = (const float*)d_in[5];
    const float* b3    = (const float*)d_in[6];
    const float* r1w1  = (const float*)d_in[7];
    const float* r1b1  = (const float*)d_in[8];
    const float* r1w2  = (const float*)d_in[9];
    const float* r1b2  = (const float*)d_in[10];
    const float* r2w1  = (const float*)d_in[11];
    const float* r2b1  = (const float*)d_in[12];
    const float* r2w2  = (const float*)d_in[13];
    const float* r2b2  = (const float*)d_in[14];
    const float* wpre  = (const float*)d_in[15];
    const float* bpre  = (const float*)d_in[16];
    const float* cbk   = (const float*)d_in[17];

    float *h2p, *h3p, *h3rp, *tp, *w2tp, *w3tp, *wr1tp, *wr2tp, *w1tp;
    cudaGetSymbolAddress((void**)&h2p,   g_h2);
    cudaGetSymbolAddress((void**)&h3p,   g_h3);
    cudaGetSymbolAddress((void**)&h3rp,  g_h3r);
    cudaGetSymbolAddress((void**)&tp,    g_t);
    cudaGetSymbolAddress((void**)&w2tp,  g_w2t);
    cudaGetSymbolAddress((void**)&w3tp,  g_w3t);
    cudaGetSymbolAddress((void**)&wr1tp, g_wr1t);
    cudaGetSymbolAddress((void**)&wr2tp, g_wr2t);
    cudaGetSymbolAddress((void**)&w1tp,  g_w1t);

    k_padw<<<1380, 256>>>(w2, w3, r1w1, r2w1, w1);
    k_conv1<<<dim3(128, 16), 128>>>(cond, w1tp, b1);
    k_conv2<<<dim3(8, 8, 16), 128>>>(w2tp, b2);
    k_c3<true, true><<<dim3(8, 8, 16), 128>>>(h2p, w3tp, b3, h3p, h3rp, 128, 128, 128, 1);

    k_c3<false, false><<<dim3(8, 2, 32), 128>>>(h3rp, wr1tp, nullptr, tp, nullptr, 32, 128, 64, 2);
    k_res1x1_add<<<dim3(64, 2, 16), 64>>>(r1w2, r1b2, r1b1);

    k_c3<false, false><<<dim3(8, 2, 32), 128>>>(h3rp, wr2tp, nullptr, tp, nullptr, 32, 128, 64, 2);
    k_res1x1z<<<dim3(64, 16), 64>>>(r2w2, r2b2, r2b1, wpre, bpre);

    k_vq<<<dim3(8, 16), 256>>>(cbk, (float*)d_out);
}

// round 9
// speedup vs baseline: 1.0948x; 1.0176x over previous
#include <cuda_runtime.h>
#include <cuda_pipeline.h>

typedef unsigned long long u64;

// ---- packed f32x2 helpers (exact IEEE fp32 per lane) ---------------------------
__device__ __forceinline__ u64 pk2(float lo, float hi) {
    u64 r; asm("mov.b64 %0, {%1, %2};" : "=l"(r) : "f"(lo), "f"(hi)); return r;
}
__device__ __forceinline__ void fma2(u64& d, u64 a, u64 b) {
    asm("fma.rn.f32x2 %0, %1, %2, %3;" : "=l"(d) : "l"(a), "l"(b), "l"(d));
}
__device__ __forceinline__ float2 up2(u64 v) {
    float lo, hi; asm("mov.b64 {%0, %1}, %2;" : "=f"(lo), "=f"(hi) : "l"(v));
    return make_float2(lo, hi);
}

// ---------------- scratch (static device globals; no allocation) ----------------
__device__ float g_h1 [16 * 64 * 128 * 128];
__device__ float g_h2 [16 * 128 * 64 * 64];
__device__ float g_h3 [16 * 128 * 64 * 64];
__device__ float g_h3r[16 * 128 * 64 * 64];
__device__ float g_t  [4 * 16 * 32 * 64 * 64];   // 4 ci-quarter partials
__device__ float g_z  [16 * 4096 * 4];
// weights transposed to [ci][kh][kw][oc] (oc contiguous -> natural u64 oc-pairs)
__device__ float g_w2t [64 * 4 * 4 * 128];
__device__ float g_w3t [128 * 3 * 3 * 128];
__device__ float g_wr1t[128 * 3 * 3 * 32];
__device__ float g_wr2t[128 * 3 * 3 * 32];
__device__ float g_w1t [16 * 64];             // conv1: [tap][oc]

// ------------- transpose weights to oc-innermost --------------------------------
__global__ void k_padw(const float* __restrict__ w2, const float* __restrict__ w3,
                       const float* __restrict__ r1, const float* __restrict__ r2,
                       const float* __restrict__ w1) {
    const int i = blockIdx.x * 256 + threadIdx.x;
    if (i < 131072) {                      // conv2: [oc128][ci64][kh4][kw4]
        const int oc = i >> 10, r = i & 1023;          // r = ci*16 + kh*4 + kw
        g_w2t[r * 128 + oc] = w2[i];
    } else if (i < 131072 + 147456) {      // conv3: [oc128][ci128][9]
        const int j = i - 131072, oc = j / 1152, r = j % 1152;
        g_w3t[r * 128 + oc] = w3[j];
    } else if (i < 131072 + 147456 + 36864) {
        const int j = i - 131072 - 147456, oc = j / 1152, r = j % 1152;
        g_wr1t[r * 32 + oc] = r1[j];
    } else if (i < 131072 + 147456 + 73728) {
        const int j = i - 131072 - 147456 - 36864, oc = j / 1152, r = j % 1152;
        g_wr2t[r * 32 + oc] = r2[j];
    } else if (i < 131072 + 147456 + 73728 + 1024) {
        const int j = i - 131072 - 147456 - 73728, oc = j >> 4, r = j & 15;
        g_w1t[r * 64 + oc] = w1[j];
    }
}

// ------- conv1 (FFMA2 oc-pairs): [16,1,256,256] -> relu -> [16,64,128,128] ------
__global__ void k_conv1(const float* __restrict__ x, const float* __restrict__ wt,
                        const float* __restrict__ b) {
    const int oy = blockIdx.x, bb = blockIdx.y, ox = threadIdx.x;
    __shared__ __align__(16) float sw[16][64];   // [tap][oc]
    __shared__ float sb[64];
    for (int i = threadIdx.x; i < 1024; i += 128) sw[i >> 6][i & 63] = wt[i];
    if (threadIdx.x < 64) sb[threadIdx.x] = b[threadIdx.x];
    __syncthreads();

    const float* xb = x + bb * 256 * 256;
    float iv[16];
#pragma unroll
    for (int kh = 0; kh < 4; kh++) {
        const int iy = 2 * oy - 1 + kh;
#pragma unroll
        for (int kw = 0; kw < 4; kw++) {
            const int ix = 2 * ox - 1 + kw;
            iv[kh * 4 + kw] = (iy >= 0 && iy < 256 && ix >= 0 && ix < 256)
                                  ? xb[iy * 256 + ix] : 0.f;
        }
    }
    u64 acc[32];
#pragma unroll
    for (int j = 0; j < 32; j++) acc[j] = pk2(sb[2 * j], sb[2 * j + 1]);
#pragma unroll
    for (int t = 0; t < 16; t++) {
        const u64 vv = pk2(iv[t], iv[t]);
        const u64* wr = (const u64*)&sw[t][0];
#pragma unroll
        for (int j = 0; j < 32; j++) fma2(acc[j], vv, wr[j]);
    }
    float* ob = g_h1 + bb * 64 * 16384 + oy * 128 + ox;
#pragma unroll
    for (int j = 0; j < 32; j++) {
        const float2 f = up2(acc[j]);
        ob[(2 * j) * 16384]     = fmaxf(f.x, 0.f);
        ob[(2 * j + 1) * 16384] = fmaxf(f.y, 0.f);
    }
}

// ---------------- conv2: k4 s2 p1, FFMA2 over oc pairs --------------------------
// block 128 = 16 xg (4px) x 8 rows; 16oc x 4px per thread
__global__ __launch_bounds__(128) void k_conv2(const float* __restrict__ wt,
                                               const float* __restrict__ b) {
    // grid (8 oy-tiles, 8 ocg, 16 batch)
    const int oy0 = blockIdx.x * 8, ocb = blockIdx.y * 16, bb = blockIdx.z;
    const int tid = threadIdx.x, txx = tid & 15, tyy = tid >> 4;

    __shared__ __align__(16) float s_in[2][2][18][136];  // interior [4..131]
    __shared__ __align__(16) float s_w [2][2][4][4][16]; // [ci][kh][kw][oc]

    for (int i = tid; i < 2 * 2 * 18; i += 128) {
        const int bf = i / 36, r = i % 36, ci = r / 18, row = r % 18;
        s_in[bf][ci][row][3]   = 0.f;
        s_in[bf][ci][row][132] = 0.f;
    }

    const float* inb = g_h1 + bb * 64 * 16384;

    auto stage = [&](int it, int bf) {
        const int c0 = it * 2;
        for (int i = tid; i < 1152; i += 128) {  // 2ci x 18row x 32 seg
            const int ci = i / 576, r = i % 576, row = r / 32, seg = r % 32;
            const int iy = 2 * oy0 - 1 + row;
            float* dst = &s_in[bf][ci][row][4 + seg * 4];
            if (iy >= 0 && iy < 128)
                __pipeline_memcpy_async(dst, inb + (c0 + ci) * 16384 + iy * 128 + seg * 4, 16);
            else
                *(float4*)dst = make_float4(0.f, 0.f, 0.f, 0.f);
        }
        for (int i = tid; i < 128; i += 128) {   // 2ci x 16 taps x 4 quads
            const int row = i >> 2, q = i & 3;   // row = ci*16 + kh*4 + kw
            __pipeline_memcpy_async(&((float*)s_w[bf])[row * 16 + q * 4],
                                    wt + (c0 * 16 + row) * 128 + ocb + q * 4, 16);
        }
    };

    u64 acc[8][4];  // [oc pair][px]
#pragma unroll
    for (int j = 0; j < 8; j++) {
        const u64 bv = pk2(b[ocb + 2 * j], b[ocb + 2 * j + 1]);
#pragma unroll
        for (int p = 0; p < 4; p++) acc[j][p] = bv;
    }

    stage(0, 0);
    __pipeline_commit();
    int cur = 0;
    for (int it = 0; it < 32; it++) {
        __pipeline_wait_prior(0);
        __syncthreads();
        if (it + 1 < 32) { stage(it + 1, cur ^ 1); __pipeline_commit(); }
#pragma unroll
        for (int ci = 0; ci < 2; ci++) {
#pragma unroll
            for (int kh = 0; kh < 4; kh++) {
                const float* rp = &s_in[cur][ci][2 * tyy + kh][8 * txx];
                const float4 A = *(const float4*)rp;
                const float4 B = *(const float4*)(rp + 4);
                const float4 C = *(const float4*)(rp + 8);
                const float  D = rp[12];
                u64 bv[10];
                bv[0] = pk2(A.w, A.w); bv[1] = pk2(B.x, B.x);
                bv[2] = pk2(B.y, B.y); bv[3] = pk2(B.z, B.z);
                bv[4] = pk2(B.w, B.w); bv[5] = pk2(C.x, C.x);
                bv[6] = pk2(C.y, C.y); bv[7] = pk2(C.z, C.z);
                bv[8] = pk2(C.w, C.w); bv[9] = pk2(D, D);
#pragma unroll
                for (int kw = 0; kw < 4; kw++) {
                    const u64* wb = (const u64*)&s_w[cur][ci][kh][kw][0];
                    const ulonglong2 W0 = *(const ulonglong2*)wb;
                    const ulonglong2 W1 = *(const ulonglong2*)(wb + 2);
                    const ulonglong2 W2 = *(const ulonglong2*)(wb + 4);
                    const ulonglong2 W3 = *(const ulonglong2*)(wb + 6);
                    const u64 w[8] = {W0.x, W0.y, W1.x, W1.y, W2.x, W2.y, W3.x, W3.y};
#pragma unroll
                    for (int j = 0; j < 8; j++)
#pragma unroll
                        for (int p = 0; p < 4; p++)
                            fma2(acc[j][p], bv[2 * p + kw], w[j]);
                }
            }
        }
        cur ^= 1;
    }
    float* ob = g_h2 + (bb * 128 + ocb) * 4096 + (oy0 + tyy) * 64 + 4 * txx;
#pragma unroll
    for (int j = 0; j < 8; j++) {
        const float2 f0 = up2(acc[j][0]), f1 = up2(acc[j][1]);
        const float2 f2 = up2(acc[j][2]), f3 = up2(acc[j][3]);
        *(float4*)(ob + (2 * j) * 4096) = make_float4(
            fmaxf(f0.x, 0.f), fmaxf(f1.x, 0.f), fmaxf(f2.x, 0.f), fmaxf(f3.x, 0.f));
        *(float4*)(ob + (2 * j + 1) * 4096) = make_float4(
            fmaxf(f0.y, 0.f), fmaxf(f1.y, 0.f), fmaxf(f2.y, 0.f), fmaxf(f3.y, 0.f));
    }
}

// ------- generic 3x3 s1 p1 conv on 64x64, FFMA2 over oc pairs -------------------
// block 128 = 16 xg (4px) x 8 rows; 16oc x 4px per thread
template <bool ADD_BIAS, bool WRITE_RELU>
__global__ __launch_bounds__(128) void k_c3(
    const float* __restrict__ in, const float* __restrict__ wt,
    const float* __restrict__ bias, float* __restrict__ out,
    float* __restrict__ outr, int COUT, int CIN_TOTAL, int CI_COUNT, int NSPLIT) {
    // grid (8 oy-tiles, COUT/16, 16*NSPLIT)
    const int oy0 = blockIdx.x * 8, ocb = blockIdx.y * 16;
    const int half = blockIdx.z % NSPLIT, bb = blockIdx.z / NSPLIT;
    const int ci0 = half * CI_COUNT;
    const int tid = threadIdx.x, txx = tid & 15, tyy = tid >> 4;

    __shared__ __align__(16) float s_in[2][4][10][72];    // interior [4..67]
    __shared__ __align__(16) float s_w [2][4][3][3][16];  // [ci][kh][kw][oc]

    for (int i = tid; i < 2 * 4 * 10; i += 128) {
        const int bf = i / 40, r = i % 40, ci = r / 10, row = r % 10;
        s_in[bf][ci][row][3]  = 0.f;
        s_in[bf][ci][row][68] = 0.f;
    }

    const float* inb = in + bb * CIN_TOTAL * 4096;

    auto stage = [&](int it, int bf) {
        const int c0 = ci0 + it * 4;
        for (int i = tid; i < 640; i += 128) {   // 4ci x 10row x 16 seg
            const int ci = i / 160, r = i % 160, row = r / 16, seg = r % 16;
            const int iy = oy0 - 1 + row;
            float* dst = &s_in[bf][ci][row][4 + seg * 4];
            if (iy >= 0 && iy < 64)
                __pipeline_memcpy_async(dst, inb + (c0 + ci) * 4096 + iy * 64 + seg * 4, 16);
            else
                *(float4*)dst = make_float4(0.f, 0.f, 0.f, 0.f);
        }
        for (int i = tid; i < 144; i += 128) {   // 4ci x 9 taps x 4 quads
            const int row = i >> 2, q = i & 3;   // row = ci*9 + kh*3 + kw
            __pipeline_memcpy_async(&((float*)s_w[bf])[row * 16 + q * 4],
                                    wt + (c0 * 9 + row) * COUT + ocb + q * 4, 16);
        }
    };

    u64 acc[8][4];
#pragma unroll
    for (int j = 0; j < 8; j++) {
        const float b0 = ADD_BIAS ? bias[ocb + 2 * j] : 0.f;
        const float b1 = ADD_BIAS ? bias[ocb + 2 * j + 1] : 0.f;
        const u64 bv = pk2(b0, b1);
#pragma unroll
        for (int p = 0; p < 4; p++) acc[j][p] = bv;
    }

    const int NITER = CI_COUNT / 4;
    stage(0, 0);
    __pipeline_commit();
    int cur = 0;
    for (int it = 0; it < NITER; it++) {
        __pipeline_wait_prior(0);
        __syncthreads();
        if (it + 1 < NITER) { stage(it + 1, cur ^ 1); __pipeline_commit(); }
#pragma unroll
        for (int ci = 0; ci < 4; ci++) {
#pragma unroll
            for (int kh = 0; kh < 3; kh++) {
                const float* rp = &s_in[cur][ci][tyy + kh][4 * txx];
                const float4 A = *(const float4*)rp;
                const float4 B = *(const float4*)(rp + 4);
                const float  E = rp[8];
                u64 bv[6];
                bv[0] = pk2(A.w, A.w); bv[1] = pk2(B.x, B.x);
                bv[2] = pk2(B.y, B.y); bv[3] = pk2(B.z, B.z);
                bv[4] = pk2(B.w, B.w); bv[5] = pk2(E, E);
#pragma unroll
                for (int kw = 0; kw < 3; kw++) {
                    const u64* wb = (const u64*)&s_w[cur][ci][kh][kw][0];
                    const ulonglong2 W0 = *(const ulonglong2*)wb;
                    const ulonglong2 W1 = *(const ulonglong2*)(wb + 2);
                    const ulonglong2 W2 = *(const ulonglong2*)(wb + 4);
                    const ulonglong2 W3 = *(const ulonglong2*)(wb + 6);
                    const u64 w[8] = {W0.x, W0.y, W1.x, W1.y, W2.x, W2.y, W3.x, W3.y};
#pragma unroll
                    for (int j = 0; j < 8; j++)
#pragma unroll
                        for (int p = 0; p < 4; p++)
                            fma2(acc[j][p], bv[p + kw], w[j]);
                }
            }
        }
        cur ^= 1;
    }
    const int off = ((half * 16 + bb) * COUT + ocb) * 4096 + (oy0 + tyy) * 64 + 4 * txx;
#pragma unroll
    for (int j = 0; j < 8; j++) {
        const float2 f0 = up2(acc[j][0]), f1 = up2(acc[j][1]);
        const float2 f2 = up2(acc[j][2]), f3 = up2(acc[j][3]);
        const float4 v0 = make_float4(f0.x, f1.x, f2.x, f3.x);
        const float4 v1 = make_float4(f0.y, f1.y, f2.y, f3.y);
        *(float4*)(out + off + (2 * j) * 4096) = v0;
        *(float4*)(out + off + (2 * j + 1) * 4096) = v1;
        if (WRITE_RELU) {
            *(float4*)(outr + off + (2 * j) * 4096) = make_float4(
                fmaxf(v0.x, 0.f), fmaxf(v0.y, 0.f), fmaxf(v0.z, 0.f), fmaxf(v0.w, 0.f));
            *(float4*)(outr + off + (2 * j + 1) * 4096) = make_float4(
                fmaxf(v1.x, 0.f), fmaxf(v1.y, 0.f), fmaxf(v1.z, 0.f), fmaxf(v1.w, 0.f));
        }
    }
}

// ------- residual 1x1 #1 (FFMA2): h3 += b + W*relu(t0+t1+t2+t3+bt); h3r = relu --
__global__ __launch_bounds__(64) void k_res1x1_add(const float* __restrict__ w,
                                                   const float* __restrict__ b,
                                                   const float* __restrict__ bt) {
    // grid (xyg=64, ocg=2, b=16), block 64 (one px per thread, 64 oc)
    const int xy0 = blockIdx.x * 64, ocb = blockIdx.y * 64, bb = blockIdx.z, tx = threadIdx.x;
    __shared__ float s_t[32][64];
    __shared__ __align__(16) float s_w[32][64];   // [ci][oc] -> u64 oc-pairs

    const float* t0 = g_t + (0 * 16 + bb) * 32 * 4096 + xy0;
    const float* t1 = g_t + (1 * 16 + bb) * 32 * 4096 + xy0;
    const float* t2 = g_t + (2 * 16 + bb) * 32 * 4096 + xy0;
    const float* t3 = g_t + (3 * 16 + bb) * 32 * 4096 + xy0;
    for (int i = tx; i < 32 * 64; i += 64) {
        const int ci = i / 64, xx = i % 64;
        s_t[ci][xx] = fmaxf(t0[ci * 4096 + xx] + t1[ci * 4096 + xx]
                          + t2[ci * 4096 + xx] + t3[ci * 4096 + xx] + bt[ci], 0.f);
    }
    for (int i = tx; i < 64 * 32; i += 64) {
        const int o = i / 32, ci = i % 32;
        s_w[ci][o] = w[(ocb + o) * 32 + ci];
    }
    __syncthreads();

    u64 acc[32];
#pragma unroll
    for (int j = 0; j < 32; j++) acc[j] = pk2(b[ocb + 2 * j], b[ocb + 2 * j + 1]);

#pragma unroll 4
    for (int ci = 0; ci < 32; ci++) {
        const float v = s_t[ci][tx];
        const u64 vv = pk2(v, v);
        const u64* wr = (const u64*)&s_w[ci][0];
#pragma unroll
        for (int j = 0; j < 32; j++) fma2(acc[j], vv, wr[j]);
    }

    float* hb  = g_h3  + (bb * 128 + ocb) * 4096 + xy0 + tx;
    float* hrb = g_h3r + (bb * 128 + ocb) * 4096 + xy0 + tx;
#pragma unroll
    for (int j = 0; j < 32; j++) {
        const float2 f = up2(acc[j]);
        const float h0 = hb[(2 * j) * 4096] + f.x;
        const float h1 = hb[(2 * j + 1) * 4096] + f.y;
        hb[(2 * j) * 4096]      = h0;
        hb[(2 * j + 1) * 4096]  = h1;
        hrb[(2 * j) * 4096]     = fmaxf(h0, 0.f);
        hrb[(2 * j + 1) * 4096] = fmaxf(h1, 0.f);
    }
}

// ------- fused res-block-2 1x1 + pre-VQ: z = Wz*relu(h3 + b + W*relu(t)) + bz ---
__global__ __launch_bounds__(64) void k_res1x1z(const float* __restrict__ w,
                                                const float* __restrict__ b,
                                                const float* __restrict__ bt,
                                                const float* __restrict__ wz,
                                                const float* __restrict__ bz) {
    // grid (xyg=64, b=16), block 64: one px per thread, ALL 128 oc
    const int xy0 = blockIdx.x * 64, bb = blockIdx.y, tx = threadIdx.x;
    __shared__ float s_t[32][64];
    __shared__ __align__(16) float s_w [32][128];  // [ci][oc]
    __shared__ __align__(16) float s_wz[128][4];   // [ci][oc4]

    const float* t0 = g_t + (0 * 16 + bb) * 32 * 4096 + xy0;
    const float* t1 = g_t + (1 * 16 + bb) * 32 * 4096 + xy0;
    const float* t2 = g_t + (2 * 16 + bb) * 32 * 4096 + xy0;
    const float* t3 = g_t + (3 * 16 + bb) * 32 * 4096 + xy0;
    for (int i = tx; i < 32 * 64; i += 64) {
        const int ci = i / 64, xx = i % 64;
        s_t[ci][xx] = fmaxf(t0[ci * 4096 + xx] + t1[ci * 4096 + xx]
                          + t2[ci * 4096 + xx] + t3[ci * 4096 + xx] + bt[ci], 0.f);
    }
    for (int i = tx; i < 128 * 32; i += 64) {
        const int o = i / 32, ci = i % 32;
        s_w[ci][o] = w[o * 32 + ci];
    }
    for (int i = tx; i < 512; i += 64) s_wz[i & 127][i >> 7] = wz[(i >> 7) * 128 + (i & 127)];
    __syncthreads();

    u64 acc[64];
#pragma unroll
    for (int j = 0; j < 64; j++) acc[j] = pk2(b[2 * j], b[2 * j + 1]);

#pragma unroll 4
    for (int ci = 0; ci < 32; ci++) {
        const float v = s_t[ci][tx];
        const u64 vv = pk2(v, v);
        const u64* wr = (const u64*)&s_w[ci][0];
#pragma unroll
        for (int j = 0; j < 64; j++) fma2(acc[j], vv, wr[j]);
    }

    // h = h3 + acc (raw h3 from res-block 1); z = Wz * relu(h) + bz, ci ascending
    const float* hb = g_h3 + bb * 128 * 4096 + xy0 + tx;
    u64 a01 = pk2(bz[0], bz[1]), a23 = pk2(bz[2], bz[3]);
#pragma unroll
    for (int j = 0; j < 64; j++) {
        const float2 f = up2(acc[j]);
        const float h0 = fmaxf(hb[(2 * j) * 4096] + f.x, 0.f);
        const float h1 = fmaxf(hb[(2 * j + 1) * 4096] + f.y, 0.f);
        const u64* wr0 = (const u64*)&s_wz[2 * j][0];
        const u64* wr1 = (const u64*)&s_wz[2 * j + 1][0];
        const u64 v0 = pk2(h0, h0), v1 = pk2(h1, h1);
        fma2(a01, v0, wr0[0]); fma2(a23, v0, wr0[1]);
        fma2(a01, v1, wr1[0]); fma2(a23, v1, wr1[1]);
    }
    const float2 f01 = up2(a01), f23 = up2(a23);
    ((float4*)g_z)[bb * 4096 + xy0 + tx] = make_float4(f01.x, f01.y, f23.x, f23.y);
}

// ------- cosine VQ: argmax_k <z, e_k/||e_k||>, gather codebook ------------------
__global__ void k_vq(const float* __restrict__ cb, float* __restrict__ out) {
    // grid (16, 16), block 256: one position per thread
    const int bb = blockIdx.y;
    const int p0 = blockIdx.x * 256 + threadIdx.x;
    __shared__ float4 s_en[2048];
    for (int k = threadIdx.x; k < 2048; k += 256) {
        const float4 c = ((const float4*)cb)[k];
        const float n = sqrtf(c.x * c.x + c.y * c.y + c.z * c.z + c.w * c.w);
        const float inv = 1.f / (n + 1e-12f);
        s_en[k] = make_float4(c.x * inv, c.y * inv, c.z * inv, c.w * inv);
    }
    __syncthreads();

    const float4 z = ((const float4*)g_z)[bb * 4096 + p0];
    float best = -1e30f;
    int bi = 0;
#pragma unroll 8
    for (int k = 0; k < 2048; k++) {
        const float4 e = s_en[k];
        const float s = z.x * e.x + z.y * e.y + z.z * e.z + z.w * e.w;
        if (s > best) { best = s; bi = k; }  // strict >: first max (JAX)
    }
    const float4 q = ((const float4*)cb)[bi];
    float* ob = out + bb * 4 * 4096 + p0;
    ob[0]        = q.x;
    ob[4096]     = q.y;
    ob[2 * 4096] = q.z;
    ob[3 * 4096] = q.w;
}

// --------------------------------- launcher -------------------------------------
extern "C" void kernel_launch(void* const* d_in, const int* in_sizes, int n_in,
                              void* d_out, int out_size) {
    const float* cond  = (const float*)d_in[0];
    const float* w1    = (const float*)d_in[1];
    const float* b1    = (const float*)d_in[2];
    const float* w2    = (const float*)d_in[3];
    const float* b2    = (const float*)d_in[4];
    const float* w3    = (const float*)d_in[5];
    const float* b3    = (const float*)d_in[6];
    const float* r1w1  = (const float*)d_in[7];
    const float* r1b1  = (const float*)d_in[8];
    const float* r1w2  = (const float*)d_in[9];
    const float* r1b2  = (const float*)d_in[10];
    const float* r2w1  = (const float*)d_in[11];
    const float* r2b1  = (const float*)d_in[12];
    const float* r2w2  = (const float*)d_in[13];
    const float* r2b2  = (const float*)d_in[14];
    const float* wpre  = (const float*)d_in[15];
    const float* bpre  = (const float*)d_in[16];
    const float* cbk   = (const float*)d_in[17];

    float *h2p, *h3p, *h3rp, *tp, *w2tp, *w3tp, *wr1tp, *wr2tp, *w1tp;
    cudaGetSymbolAddress((void**)&h2p,   g_h2);
    cudaGetSymbolAddress((void**)&h3p,   g_h3);
    cudaGetSymbolAddress((void**)&h3rp,  g_h3r);
    cudaGetSymbolAddress((void**)&tp,    g_t);
    cudaGetSymbolAddress((void**)&w2tp,  g_w2t);
    cudaGetSymbolAddress((void**)&w3tp,  g_w3t);
    cudaGetSymbolAddress((void**)&wr1tp, g_wr1t);
    cudaGetSymbolAddress((void**)&wr2tp, g_wr2t);
    cudaGetSymbolAddress((void**)&w1tp,  g_w1t);

    k_padw<<<1380, 256>>>(w2, w3, r1w1, r2w1, w1);
    k_conv1<<<dim3(128, 16), 128>>>(cond, w1tp, b1);
    k_conv2<<<dim3(8, 8, 16), 128>>>(w2tp, b2);
    k_c3<true, true><<<dim3(8, 8, 16), 128>>>(h2p, w3tp, b3, h3p, h3rp, 128, 128, 128, 1);

    // res-block 1: 3x3 split 4-ways over ci (grid 1024 fills 592 slots at 1.73x)
    k_c3<false, false><<<dim3(8, 2, 64), 128>>>(h3rp, wr1tp, nullptr, tp, nullptr, 32, 128, 32, 4);
    k_res1x1_add<<<dim3(64, 2, 16), 64>>>(r1w2, r1b2, r1b1);

    // res-block 2: same split; 1x1 fused with pre-VQ projection
    k_c3<false, false><<<dim3(8, 2, 64), 128>>>(h3rp, wr2tp, nullptr, tp, nullptr, 32, 128, 32, 4);
    k_res1x1z<<<dim3(64, 16), 64>>>(r2w2, r2b2, r2b1, wpre, bpre);

    k_vq<<<dim3(16, 16), 256>>>(cbk, (float*)d_out);
}